// round 15
// baseline (speedup 1.0000x reference)
#include <cuda_runtime.h>
#include <cuda_bf16.h>
#include <math.h>
#include <stdint.h>

// Problem dims
#define B_ 16
#define S_ 80
#define L_ 200
#define E_ 512
#define M_ 1024
#define T_ 1024
#define H_ 512
#define V_ 10000

#define NBLK_LSTM 128

// ---------------- scratch (device globals; no allocation allowed) ----------------
__device__ float g_tmpM[B_ * S_ * M_];
__device__ float g_tmpT[B_ * S_ * T_];
__device__ float g_xproj[(B_ * S_ + B_ * 8) * 4 * H_];
__device__ float g_meanfeat[B_ * 8 * 204];
__device__ float g_bsum[4 * H_];
__device__ float g_hA[B_ * H_];     // h layout: [bg][k][4]
__device__ float g_hB[B_ * H_];
__device__ float g_attw[2 * B_ * L_];
__device__ float g_ctxT[2048 * B_];
__device__ float g_ctxpart[4 * B_ * V_];
__device__ float g_ctxproj[B_ * V_];
__device__ unsigned g_barcnt4[4 * 32];   // per-group barrier counters, 128B apart

// bf16 operands
__device__ __nv_bfloat16 g_amot_bf[B_ * S_ * M_];
__device__ __nv_bfloat16 g_atem_bf[B_ * S_ * T_];
__device__ __nv_bfloat16 g_Wm_bf[M_ * M_];
__device__ __nv_bfloat16 g_Wt_bf[T_ * T_];
__device__ __nv_bfloat16 g_Wmm_bf[H_ * 2560];
__device__ __nv_bfloat16 g_Wih_bf[4 * H_ * H_];
__device__ __nv_bfloat16 g_Wo_bf[V_ * H_];          // Wo[:, 0:512]
__device__ __nv_bfloat16 g_mminp_bf[B_ * S_ * 2560];
__device__ __nv_bfloat16 g_xin_bf[(B_ * S_ + B_ * 8) * H_];
__device__ __nv_bfloat16 g_act_bf[B_ * S_ * H_];

// ---------------- reductions ----------------
__device__ __forceinline__ float warpRedMax(float v) {
    #pragma unroll
    for (int o = 16; o > 0; o >>= 1) v = fmaxf(v, __shfl_xor_sync(0xffffffffu, v, o));
    return v;
}
__device__ __forceinline__ float warpRedSum(float v) {
    #pragma unroll
    for (int o = 16; o > 0; o >>= 1) v += __shfl_xor_sync(0xffffffffu, v, o);
    return v;
}
__device__ __forceinline__ float blockReduceMax(float v, float* red) {
    int w = threadIdx.x >> 5, l = threadIdx.x & 31;
    int nw = (blockDim.x + 31) >> 5;
    v = warpRedMax(v);
    __syncthreads();
    if (l == 0) red[w] = v;
    __syncthreads();
    v = (l < nw) ? red[l] : -1e30f;
    return warpRedMax(v);
}
__device__ __forceinline__ float blockReduceSum(float v, float* red) {
    int w = threadIdx.x >> 5, l = threadIdx.x & 31;
    int nw = (blockDim.x + 31) >> 5;
    v = warpRedSum(v);
    __syncthreads();
    if (l == 0) red[w] = v;
    __syncthreads();
    v = (l < nw) ? red[l] : 0.f;
    return warpRedSum(v);
}

// ---------------- mma.sync bf16 primitive ----------------
__device__ __forceinline__ void mma16816(float* c, const uint32_t* a, uint32_t b0, uint32_t b1)
{
    asm volatile(
        "mma.sync.aligned.m16n8k16.row.col.f32.bf16.bf16.f32 "
        "{%0,%1,%2,%3}, {%4,%5,%6,%7}, {%8,%9}, {%0,%1,%2,%3};"
        : "+f"(c[0]), "+f"(c[1]), "+f"(c[2]), "+f"(c[3])
        : "r"(a[0]), "r"(a[1]), "r"(a[2]), "r"(a[3]), "r"(b0), "r"(b1));
}

// ---------------- HMMA bf16 GEMM: C(MxN) = A(MxK) @ B(NxK)^T ----------------
// Optional second problem via blockIdx.z (same shapes).
template<int NT>
__global__ __launch_bounds__(256) void gemm_mma(
    const __nv_bfloat16* __restrict__ A, int lda,
    const __nv_bfloat16* __restrict__ Bw, int ldb,
    const float* __restrict__ bias,
    const float* __restrict__ rowbias, int rowdiv, int rbstride,
    float* __restrict__ Cf, __nv_bfloat16* __restrict__ Cb, int ldc,
    int K,
    const __nv_bfloat16* A2 = nullptr, const __nv_bfloat16* B2 = nullptr,
    const float* bias2 = nullptr, float* Cf2 = nullptr)
{
    if (blockIdx.z == 1) { A = A2; Bw = B2; bias = bias2; Cf = Cf2; Cb = nullptr; }
    constexpr int NWT = NT / 16;
    constexpr int BUI4 = NT * 4;
    __shared__ __nv_bfloat16 sa[2][128 * 40];
    __shared__ __nv_bfloat16 sb[2][NT * 40];

    const int tid = threadIdx.x;
    const int warp = tid >> 5, lane = tid & 31;
    const int wm = warp & 3, wn = warp >> 2;
    const int gid = lane >> 2, tig = lane & 3;
    const int row0 = blockIdx.y * 128;
    const int col0 = blockIdx.x * NT;

    float acc[2][NWT][4];
    #pragma unroll
    for (int mt = 0; mt < 2; mt++)
        #pragma unroll
        for (int nt = 0; nt < NWT; nt++)
            #pragma unroll
            for (int i = 0; i < 4; i++) acc[mt][nt][i] = 0.f;

    const int nch = K >> 5;

    {
        #pragma unroll
        for (int u = 0; u < 2; u++) {
            int idx = tid + u * 256;
            int r = idx >> 2, c4 = idx & 3;
            uint4 v = *(const uint4*)(A + (size_t)(row0 + r) * lda + c4 * 8);
            *(uint4*)(&sa[0][r * 40 + c4 * 8]) = v;
        }
        #pragma unroll
        for (int u = 0; u < (BUI4 + 255) / 256; u++) {
            int idx = tid + u * 256;
            if (idx < BUI4) {
                int r = idx >> 2, c4 = idx & 3;
                uint4 v = *(const uint4*)(Bw + (size_t)(col0 + r) * ldb + c4 * 8);
                *(uint4*)(&sb[0][r * 40 + c4 * 8]) = v;
            }
        }
    }
    __syncthreads();

    for (int ch = 0; ch < nch; ch++) {
        uint4 pa[2], pb[(BUI4 + 255) / 256];
        const bool more = (ch + 1) < nch;
        if (more) {
            const int k0 = (ch + 1) << 5;
            #pragma unroll
            for (int u = 0; u < 2; u++) {
                int idx = tid + u * 256;
                int r = idx >> 2, c4 = idx & 3;
                pa[u] = *(const uint4*)(A + (size_t)(row0 + r) * lda + k0 + c4 * 8);
            }
            #pragma unroll
            for (int u = 0; u < (BUI4 + 255) / 256; u++) {
                int idx = tid + u * 256;
                if (idx < BUI4) {
                    int r = idx >> 2, c4 = idx & 3;
                    pb[u] = *(const uint4*)(Bw + (size_t)(col0 + r) * ldb + k0 + c4 * 8);
                }
            }
        }

        const __nv_bfloat16* sA = sa[ch & 1];
        const __nv_bfloat16* sB = sb[ch & 1];
        #pragma unroll
        for (int s = 0; s < 2; s++) {
            uint32_t af[2][4];
            #pragma unroll
            for (int mt = 0; mt < 2; mt++) {
                const __nv_bfloat16* p = sA + (wm * 32 + mt * 16 + gid) * 40 + s * 16 + 2 * tig;
                af[mt][0] = *(const uint32_t*)(p);
                af[mt][1] = *(const uint32_t*)(p + 8 * 40);
                af[mt][2] = *(const uint32_t*)(p + 8);
                af[mt][3] = *(const uint32_t*)(p + 8 * 40 + 8);
            }
            #pragma unroll
            for (int nt = 0; nt < NWT; nt++) {
                const __nv_bfloat16* p = sB + (wn * (NT / 2) + nt * 8 + gid) * 40 + s * 16 + 2 * tig;
                uint32_t b0 = *(const uint32_t*)(p);
                uint32_t b1 = *(const uint32_t*)(p + 8);
                mma16816(acc[0][nt], af[0], b0, b1);
                mma16816(acc[1][nt], af[1], b0, b1);
            }
        }

        if (more) {
            __nv_bfloat16* dA = sa[(ch + 1) & 1];
            __nv_bfloat16* dB = sb[(ch + 1) & 1];
            #pragma unroll
            for (int u = 0; u < 2; u++) {
                int idx = tid + u * 256;
                int r = idx >> 2, c4 = idx & 3;
                *(uint4*)(&dA[r * 40 + c4 * 8]) = pa[u];
            }
            #pragma unroll
            for (int u = 0; u < (BUI4 + 255) / 256; u++) {
                int idx = tid + u * 256;
                if (idx < BUI4) {
                    int r = idx >> 2, c4 = idx & 3;
                    *(uint4*)(&dB[r * 40 + c4 * 8]) = pb[u];
                }
            }
        }
        __syncthreads();
    }

    #pragma unroll
    for (int mt = 0; mt < 2; mt++) {
        #pragma unroll
        for (int half = 0; half < 2; half++) {
            int r = row0 + wm * 32 + mt * 16 + gid + half * 8;
            const float* rbp = rowbias ? (rowbias + (size_t)(r / rowdiv) * rbstride) : nullptr;
            #pragma unroll
            for (int nt = 0; nt < NWT; nt++) {
                int c = col0 + wn * (NT / 2) + nt * 8 + 2 * tig;
                float v0 = acc[mt][nt][half * 2 + 0];
                float v1 = acc[mt][nt][half * 2 + 1];
                if (bias) { v0 += bias[c]; v1 += bias[c + 1]; }
                if (rbp)  { v0 += rbp[c];  v1 += rbp[c + 1];  }
                if (Cf) *(float2*)(Cf + (size_t)r * ldc + c) = make_float2(v0, v1);
                if (Cb) {
                    __nv_bfloat162 p = __floats2bfloat162_rn(v0, v1);
                    *(__nv_bfloat162*)(Cb + (size_t)r * ldc + c) = p;
                }
            }
        }
    }
}

// ---------------- merged fp32 -> bf16 conversion (main-path: amot, atem, Wm, Wt) ----------------
#define F2B_N0 327680                       // amot  1280*1024/4
#define F2B_N1 (F2B_N0 + 327680)            // atem
#define F2B_N2 (F2B_N1 + 262144)            // Wm    1024*1024/4
#define F2B_N3 (F2B_N2 + 262144)            // Wt

__global__ void f2b_all_kernel(
    const float* __restrict__ s0, __nv_bfloat16* __restrict__ d0,
    const float* __restrict__ s1, __nv_bfloat16* __restrict__ d1,
    const float* __restrict__ s2p, __nv_bfloat16* __restrict__ d2,
    const float* __restrict__ s3, __nv_bfloat16* __restrict__ d3)
{
    int i = blockIdx.x * blockDim.x + threadIdx.x;
    const float* s; __nv_bfloat16* d; int off;
    if      (i < F2B_N0) { s = s0;  d = d0; off = 0; }
    else if (i < F2B_N1) { s = s1;  d = d1; off = F2B_N0; }
    else if (i < F2B_N2) { s = s2p; d = d2; off = F2B_N1; }
    else if (i < F2B_N3) { s = s3;  d = d3; off = F2B_N2; }
    else return;
    int j = i - off;
    float4 v = ((const float4*)s)[j];
    __nv_bfloat162 p0 = __floats2bfloat162_rn(v.x, v.y);
    __nv_bfloat162 p1 = __floats2bfloat162_rn(v.z, v.w);
    ((uint2*)d)[j] = make_uint2(*(uint32_t*)&p0, *(uint32_t*)&p1);
}

// s2: Wmm + Wih conversion (two buffers, one launch)
#define F2BW_N0 327680                      // Wmm 512*2560/4
#define F2BW_N1 (F2BW_N0 + 262144)          // Wih 2048*512/4
__global__ void f2b_w_kernel(
    const float* __restrict__ s0, __nv_bfloat16* __restrict__ d0,
    const float* __restrict__ s1, __nv_bfloat16* __restrict__ d1)
{
    int i = blockIdx.x * blockDim.x + threadIdx.x;
    const float* s; __nv_bfloat16* d; int off;
    if      (i < F2BW_N0) { s = s0; d = d0; off = 0; }
    else if (i < F2BW_N1) { s = s1; d = d1; off = F2BW_N0; }
    else return;
    int j = i - off;
    float4 v = ((const float4*)s)[j];
    __nv_bfloat162 p0 = __floats2bfloat162_rn(v.x, v.y);
    __nv_bfloat162 p1 = __floats2bfloat162_rn(v.z, v.w);
    ((uint2*)d)[j] = make_uint2(*(uint32_t*)&p0, *(uint32_t*)&p1);
}

// Wo[:, 0:512] strided slice -> bf16 (rows V_, src stride 2560)
__global__ void f2b_wo_kernel(const float* __restrict__ s, __nv_bfloat16* __restrict__ d)
{
    int i = blockIdx.x * blockDim.x + threadIdx.x;
    if (i >= V_ * 128) return;
    int r = i >> 7, c4 = i & 127;
    float4 v = ((const float4*)(s + (size_t)r * 2560))[c4];
    __nv_bfloat162 p0 = __floats2bfloat162_rn(v.x, v.y);
    __nv_bfloat162 p1 = __floats2bfloat162_rn(v.z, v.w);
    ((uint2*)(d + (size_t)r * 512))[c4] = make_uint2(*(uint32_t*)&p0, *(uint32_t*)&p1);
}

// ---------------- self-gating (both modalities via grid.y; y==0 also copies embeddings) ----------------
__global__ __launch_bounds__(256) void selfgate_kernel(const float* __restrict__ XT,
                                                       const float* __restrict__ XM,
                                                       const float* __restrict__ emb,
                                                       __nv_bfloat16* __restrict__ out)
{
    __shared__ float red[32];
    int row = blockIdx.x;
    const float* x = (blockIdx.y == 0 ? XT : XM) + (size_t)row * 1024;
    int colOff = blockIdx.y == 0 ? 512 : 1536;
    float xv[4];
    float m = -1e30f;
    #pragma unroll
    for (int i = 0; i < 4; i++) { xv[i] = x[threadIdx.x + i * 256]; m = fmaxf(m, xv[i]); }
    m = blockReduceMax(m, red);
    float ev[4];
    float s = 0.f;
    #pragma unroll
    for (int i = 0; i < 4; i++) { ev[i] = expf(xv[i] - m); s += ev[i]; }
    s = blockReduceSum(s, red);
    float inv = 1.f / s;
    __nv_bfloat16* o = out + (size_t)row * 2560 + colOff;
    #pragma unroll
    for (int i = 0; i < 4; i++) o[threadIdx.x + i * 256] = __float2bfloat16(xv[i] * ev[i] * inv);

    // fused embeddings copy into mm_inp[:, 0:512] (y==0 blocks; threads 0..127)
    if (blockIdx.y == 0 && threadIdx.x < 128) {
        float4 v = ((const float4*)(emb + (size_t)row * 512))[threadIdx.x];
        __nv_bfloat162 p0 = __floats2bfloat162_rn(v.x, v.y);
        __nv_bfloat162 p1 = __floats2bfloat162_rn(v.z, v.w);
        ((uint2*)(out + (size_t)row * 2560))[threadIdx.x] =
            make_uint2(*(uint32_t*)&p0, *(uint32_t*)&p1);
    }
}

__global__ void avgpool_kernel(const float* __restrict__ att_tempo,
                               const float* __restrict__ att_motion,
                               float* __restrict__ out)
{
    int c = threadIdx.x;
    if (c >= 204) return;
    int b = blockIdx.x >> 3, s8 = blockIdx.x & 7;
    const float* src = (c < 102) ? att_tempo : att_motion;
    int cc = (c < 102) ? c : c - 102;
    const float* base = src + ((size_t)(b * 80 + s8 * 10)) * 1024 + cc * 10;
    float s = 0.f;
    #pragma unroll
    for (int r = 0; r < 10; r++) {
        const float* p = base + r * 1024;
        #pragma unroll
        for (int q = 0; q < 10; q++) s += p[q];
    }
    out[(size_t)blockIdx.x * 204 + c] = s * 0.01f;
}

__global__ void gemm_naive(const float* __restrict__ A, const float* __restrict__ Bm,
                           const float* __restrict__ bias, __nv_bfloat16* __restrict__ C,
                           int M, int N, int K)
{
    int idx = blockIdx.x * blockDim.x + threadIdx.x;
    if (idx >= M * N) return;
    int m = idx / N, n = idx % N;
    const float* a = A + (size_t)m * K;
    const float* b = Bm + (size_t)n * K;
    float s = 0.f;
    for (int k = 0; k < K; k++) s += a[k] * b[k];
    C[idx] = __float2bfloat16(s + bias[n]);
}

__global__ void bsum_kernel(const float* __restrict__ a, const float* __restrict__ b,
                            float* __restrict__ o)
{
    int i = blockIdx.x * blockDim.x + threadIdx.x;
    if (i < 2048) o[i] = a[i] + b[i];
}

// ---------------- persistent LSTM v2: 32 unit-groups x 4 independent batch-groups ----------------
// Barrier (round-11 proven): threadfence + relaxed atomicAdd + thread-0 volatile spin, 32-block scope.
__device__ __forceinline__ void group_sync(int bg)
{
    __threadfence();
    __syncthreads();
    if (threadIdx.x == 0) {
        unsigned* cnt = &g_barcnt4[bg * 32];
        unsigned a = atomicAdd(cnt, 1u);
        unsigned target = (a / 32u + 1u) * 32u;
        while (true) {
            unsigned v = *(volatile unsigned*)cnt;
            if ((v - target) < 0x80000000u) break;
        }
    }
    __syncthreads();
}

// smem (floats): Wsh 512*68 = 34816 | hsh 512*4 = 2048 | red 256*17 = 4352 | gsh 256 | csh 64
#define LSTM_SMEMF (34816 + 2048 + 4352 + 256 + 64)

__global__ __launch_bounds__(256) void lstm_persistent(
    const float* __restrict__ xp,
    const float* __restrict__ Whh,
    __nv_bfloat16* __restrict__ act,
    float* __restrict__ hA, float* __restrict__ hB)
{
    extern __shared__ float sm[];
    float* Wsh = sm;                 // [k][64] stride 68, row r = u*4 + gate
    float* hsh = Wsh + 34816;        // [k][4]
    float* red = hsh + 2048;         // 256 outputs x 17
    float* gsh = red + 4352;         // 256
    float* csh = gsh + 256;          // 64 (16 units x 4 batches)

    const int bi = blockIdx.x;
    const int bg = bi & 3;           // batch group 0..3
    const int ug = bi >> 2;          // unit group 0..31
    const int t = threadIdx.x;

    for (int i = t; i < 64 * 512; i += 256) {
        int r = i >> 9, k = i & 511;
        int u = r >> 2, gate = r & 3;
        Wsh[k * 68 + r] = Whh[(size_t)(gate * 512 + ug * 16 + u) * 512 + k];
    }
    if (t < 64) csh[t] = 0.f;
    __syncthreads();

    const int kp = t & 15, tile = t >> 4;
    const int rowr = t >> 2, bl = t & 3;
    const int ur = rowr >> 2, gater = rowr & 3;
    const size_t xp_col = (size_t)(gater * 512 + ug * 16 + ur);
    const int b_global = bg * 4 + bl;
    const int hbase = bg * 2048;
    float* hb[2] = { hA, hB };

    for (int step = 0; step < 88; step++) {
        const float* hin = hb[step & 1];
        float* hout = hb[1 - (step & 1)];

        int rowidx = (step < 8) ? (1280 + b_global * 8 + step) : (b_global * 80 + (step - 8));
        float xv = __ldg(xp + (size_t)rowidx * 2048 + xp_col);

        for (int i = t; i < 512; i += 256) {
            float4 v = __ldcg(((const float4*)(hin + hbase)) + i);
            *(float4*)&hsh[i * 4] = v;
        }
        __syncthreads();

        float acc[4][4];
        #pragma unroll
        for (int i = 0; i < 4; i++)
            #pragma unroll
            for (int j = 0; j < 4; j++) acc[i][j] = 0.f;
        const float* wp = Wsh + kp * 68 + tile * 4;
        const float* hp = hsh + kp * 4;
        #pragma unroll
        for (int it = 0; it < 32; it++) {
            float4 wv = *(const float4*)(wp + it * (16 * 68));
            float4 hv = *(const float4*)(hp + it * (16 * 4));
            acc[0][0] += wv.x * hv.x; acc[0][1] += wv.x * hv.y; acc[0][2] += wv.x * hv.z; acc[0][3] += wv.x * hv.w;
            acc[1][0] += wv.y * hv.x; acc[1][1] += wv.y * hv.y; acc[1][2] += wv.y * hv.z; acc[1][3] += wv.y * hv.w;
            acc[2][0] += wv.z * hv.x; acc[2][1] += wv.z * hv.y; acc[2][2] += wv.z * hv.z; acc[2][3] += wv.z * hv.w;
            acc[3][0] += wv.w * hv.x; acc[3][1] += wv.w * hv.y; acc[3][2] += wv.w * hv.z; acc[3][3] += wv.w * hv.w;
        }
        #pragma unroll
        for (int i = 0; i < 4; i++)
            #pragma unroll
            for (int j = 0; j < 4; j++)
                red[((tile * 4 + i) * 4 + j) * 17 + kp] = acc[i][j];
        __syncthreads();

        {
            float s = 0.f;
            #pragma unroll
            for (int k2 = 0; k2 < 16; k2++) s += red[t * 17 + k2];
            gsh[t] = s + xv;
        }
        __syncthreads();

        if (t < 64) {
            int u = t >> 2, b = t & 3;
            float iv = gsh[(u * 4 + 0) * 4 + b];
            float fv = gsh[(u * 4 + 1) * 4 + b];
            float gv = gsh[(u * 4 + 2) * 4 + b];
            float ov = gsh[(u * 4 + 3) * 4 + b];
            float c = csh[t];
            float ig = 1.f / (1.f + expf(-iv));
            float fg = 1.f / (1.f + expf(-fv));
            float og = 1.f / (1.f + expf(-ov));
            float cn = fg * c + ig * tanhf(gv);
            float hn = og * tanhf(cn);
            csh[t] = cn;
            int ku = ug * 16 + u;
            hout[hbase + ku * 4 + b] = hn;
            if (step >= 8)
                act[(size_t)((bg * 4 + b) * 80 + step - 8) * 512 + ku] = __float2bfloat16(tanhf(hn));
        }
        group_sync(bg);
    }
}

// ---------------- attention scores (both modalities via grid.y) ----------------
__global__ __launch_bounds__(256) void attn_scores(
    const float* __restrict__ tf, const float* __restrict__ mf,
    const float* __restrict__ wst, const float* __restrict__ wsm,
    const int* __restrict__ tlens, const int* __restrict__ mlens,
    float* __restrict__ wout)
{
    __shared__ float sf[200];
    __shared__ float red[32];
    int b = blockIdx.x;
    const float* feat = blockIdx.y == 0 ? tf : mf;
    const float* wf = blockIdx.y == 0 ? wst : wsm;
    const int* lens = blockIdx.y == 0 ? tlens : mlens;
    float* wo = wout + blockIdx.y * 16 * 200;
    int tid = threadIdx.x, warp = tid >> 5, lane = tid & 31;
    const float* fb = feat + (size_t)b * 200 * 1024;

    for (int l = warp; l < 200; l += 8) {
        const float* fr = fb + (size_t)l * 1024;
        float s = 0.f;
        for (int k = lane; k < 1024; k += 32) s += fr[k] * wf[k];
        s = warpRedSum(s);
        if (lane == 0) sf[l] = s;
    }
    __syncthreads();
    int len = lens[b];
    float m = -1e30f;
    for (int l = tid; l < len; l += 256) m = fmaxf(m, sf[l]);
    m = blockReduceMax(m, red);
    float s = 0.f;
    for (int l = tid; l < len; l += 256) s += expf(sf[l] - m);
    s = blockReduceSum(s, red);
    float inv = 1.f / s;
    __syncthreads();
    for (int l = tid; l < 200; l += 256)
        wo[b * 200 + l] = (l < len) ? expf(sf[l] - m) * inv : 0.f;
}

// ---------------- attention context gather (both modalities via grid.z) ----------------
__global__ __launch_bounds__(128) void attn_ctx(
    const float* __restrict__ tf, const float* __restrict__ mf,
    const float* __restrict__ w, float* __restrict__ ctxT)
{
    __shared__ float ws[200];
    int b = blockIdx.x;
    int f = blockIdx.y * 128 + threadIdx.x;
    const float* feat = blockIdx.z == 0 ? tf : mf;
    const float* wp = w + blockIdx.z * 16 * 200;
    int off = blockIdx.z * 1024;
    for (int l = threadIdx.x; l < 200; l += 128) ws[l] = wp[b * 200 + l];
    __syncthreads();
    const float* fb = feat + (size_t)b * 200 * 1024 + f;
    float acc = 0.f;
    #pragma unroll 4
    for (int l = 0; l < 200; l++) acc += ws[l] * fb[(size_t)l * 1024];
    ctxT[(size_t)(off + f) * 16 + b] = acc;
}

// ---------------- ctxproj split-k: Cp[kc][b][v] = partial dot over 512-k chunk ----------------
__global__ __launch_bounds__(64) void ctxproj_part(
    const float* __restrict__ AT, const float* __restrict__ Wo,
    float* __restrict__ Cp)
{
    int tid = threadIdx.x;
    int bq = tid & 3, vl = tid >> 2;
    int v = blockIdx.x * 16 + vl;
    int kc = blockIdx.y;                       // 0..3
    const float4* w4 = (const float4*)(Wo + (size_t)v * 2560 + 512 + kc * 512);
    const float4* a4 = (const float4*)(AT + (size_t)kc * 512 * 16);
    float a0 = 0.f, a1 = 0.f, a2 = 0.f, a3 = 0.f;
    #pragma unroll 4
    for (int k4 = 0; k4 < 128; k4++) {
        float4 w = w4[k4];
        float4 x0 = a4[(k4 * 4 + 0) * 4 + bq];
        float4 x1 = a4[(k4 * 4 + 1) * 4 + bq];
        float4 x2 = a4[(k4 * 4 + 2) * 4 + bq];
        float4 x3 = a4[(k4 * 4 + 3) * 4 + bq];
        a0 += w.x * x0.x + w.y * x1.x + w.z * x2.x + w.w * x3.x;
        a1 += w.x * x0.y + w.y * x1.y + w.z * x2.y + w.w * x3.y;
        a2 += w.x * x0.z + w.y * x1.z + w.z * x2.z + w.w * x3.z;
        a3 += w.x * x0.w + w.y * x1.w + w.z * x2.w + w.w * x3.w;
    }
    float* C = Cp + (size_t)kc * 16 * V_;
    C[(size_t)(bq * 4 + 0) * V_ + v] = a0;
    C[(size_t)(bq * 4 + 1) * V_ + v] = a1;
    C[(size_t)(bq * 4 + 2) * V_ + v] = a2;
    C[(size_t)(bq * 4 + 3) * V_ + v] = a3;
}

__global__ void ctxproj_reduce(const float* __restrict__ Cp, const float* __restrict__ bo,
                               float* __restrict__ C)
{
    int i = blockIdx.x * blockDim.x + threadIdx.x;
    if (i >= 16 * V_) return;
    int v = i % V_;
    float s = bo[v];
    #pragma unroll
    for (int kc = 0; kc < 4; kc++) s += Cp[(size_t)kc * 16 * V_ + i];
    C[i] = s;
}

// ---------------- log_softmax over V (in-place) ----------------
__global__ __launch_bounds__(256) void logsoftmax_kernel(float* __restrict__ X)
{
    extern __shared__ float sh[];
    __shared__ float red[32];
    int row = blockIdx.x;
    float* x = X + (size_t)row * V_;
    float m = -1e30f;
    for (int i = threadIdx.x; i < V_; i += 256) { float v = x[i]; sh[i] = v; m = fmaxf(m, v); }
    m = blockReduceMax(m, red);
    float s = 0.f;
    for (int i = threadIdx.x; i < V_; i += 256) s += expf(sh[i] - m);
    s = blockReduceSum(s, red);
    float lse = m + logf(s);
    for (int i = threadIdx.x; i < V_; i += 256) x[i] = sh[i] - lse;
}

// ---------------- host ----------------
extern "C" void kernel_launch(void* const* d_in, const int* in_sizes, int n_in,
                              void* d_out, int out_size)
{
    (void)in_sizes; (void)n_in; (void)out_size;
    const float* mfeat       = (const float*)d_in[0];
    const float* tfeat       = (const float*)d_in[1];
    const float* att_motion  = (const float*)d_in[2];
    const float* att_tempo   = (const float*)d_in[3];
    const float* embeddings  = (const float*)d_in[4];
    const int*   mlens       = (const int*)d_in[5];
    const int*   tlens       = (const int*)d_in[6];
    const float* Wm   = (const float*)d_in[8];
    const float* bm   = (const float*)d_in[9];
    const float* Wt   = (const float*)d_in[10];
    const float* bt   = (const float*)d_in[11];
    const float* Wmm  = (const float*)d_in[12];
    const float* bmm  = (const float*)d_in[13];
    const float* Wli  = (const float*)d_in[14];
    const float* bli  = (const float*)d_in[15];
    const float* Wih  = (const float*)d_in[16];
    const float* Whh  = (const float*)d_in[17];
    const float* bih  = (const float*)d_in[18];
    const float* bhh  = (const float*)d_in[19];
    const float* Wsm  = (const float*)d_in[20];
    const float* Wst  = (const float*)d_in[22];
    const float* Wo   = (const float*)d_in[24];
    const float* bo   = (const float*)d_in[25];
    float* out = (float*)d_out;

    float *tmpM, *tmpT, *xproj, *meanfeat, *bsum, *hA, *hB, *attw, *ctxT, *ctxpart, *ctxproj;
    __nv_bfloat16 *amot_bf, *atem_bf, *Wm_bf, *Wt_bf, *Wmm_bf, *Wih_bf, *Wo_bf;
    __nv_bfloat16 *mminp_bf, *xin_bf, *act_bf;
    cudaGetSymbolAddress((void**)&tmpM, g_tmpM);
    cudaGetSymbolAddress((void**)&tmpT, g_tmpT);
    cudaGetSymbolAddress((void**)&xproj, g_xproj);
    cudaGetSymbolAddress((void**)&meanfeat, g_meanfeat);
    cudaGetSymbolAddress((void**)&bsum, g_bsum);
    cudaGetSymbolAddress((void**)&hA, g_hA);
    cudaGetSymbolAddress((void**)&hB, g_hB);
    cudaGetSymbolAddress((void**)&attw, g_attw);
    cudaGetSymbolAddress((void**)&ctxT, g_ctxT);
    cudaGetSymbolAddress((void**)&ctxpart, g_ctxpart);
    cudaGetSymbolAddress((void**)&ctxproj, g_ctxproj);
    cudaGetSymbolAddress((void**)&amot_bf, g_amot_bf);
    cudaGetSymbolAddress((void**)&atem_bf, g_atem_bf);
    cudaGetSymbolAddress((void**)&Wm_bf, g_Wm_bf);
    cudaGetSymbolAddress((void**)&Wt_bf, g_Wt_bf);
    cudaGetSymbolAddress((void**)&Wmm_bf, g_Wmm_bf);
    cudaGetSymbolAddress((void**)&Wih_bf, g_Wih_bf);
    cudaGetSymbolAddress((void**)&Wo_bf, g_Wo_bf);
    cudaGetSymbolAddress((void**)&mminp_bf, g_mminp_bf);
    cudaGetSymbolAddress((void**)&xin_bf, g_xin_bf);
    cudaGetSymbolAddress((void**)&act_bf, g_act_bf);

    const int lstm_smem = LSTM_SMEMF * (int)sizeof(float);
    cudaFuncSetAttribute(lstm_persistent, cudaFuncAttributeMaxDynamicSharedMemorySize, lstm_smem);

    static cudaStream_t s2 = nullptr;
    static cudaEvent_t evF = nullptr, evW = nullptr, evJ = nullptr;
    if (!s2) {
        cudaStreamCreateWithFlags(&s2, cudaStreamNonBlocking);
        cudaEventCreateWithFlags(&evF, cudaEventDisableTiming);
        cudaEventCreateWithFlags(&evW, cudaEventDisableTiming);
        cudaEventCreateWithFlags(&evJ, cudaEventDisableTiming);
    }

    // ---- fork: Wmm/Wih conversion + attention path on s2 (depends only on inputs) ----
    cudaEventRecord(evF, 0);
    cudaStreamWaitEvent(s2, evF, 0);
    f2b_w_kernel<<<(F2BW_N1 + 255) / 256, 256, 0, s2>>>(Wmm, Wmm_bf, Wih, Wih_bf);
    cudaEventRecord(evW, s2);
    f2b_wo_kernel<<<(V_ * 128 + 255) / 256, 256, 0, s2>>>(Wo, Wo_bf);
    attn_scores<<<dim3(16, 2), 256, 0, s2>>>(tfeat, mfeat, Wst + 512, Wsm + 512, tlens, mlens, attw);
    attn_ctx<<<dim3(16, 8, 2), 128, 0, s2>>>(tfeat, mfeat, attw, ctxT);
    ctxproj_part<<<dim3(625, 4), 64, 0, s2>>>(ctxT, Wo, ctxpart);
    ctxproj_reduce<<<(16 * V_ + 255) / 256, 256, 0, s2>>>(ctxpart, bo, ctxproj);
    cudaEventRecord(evJ, s2);

    // ---- main path ----
    f2b_all_kernel<<<(F2B_N3 + 255) / 256, 256>>>(
        att_motion, amot_bf, att_tempo, atem_bf, Wm, Wm_bf, Wt, Wt_bf);

    bsum_kernel<<<8, 256>>>(bih, bhh, bsum);
    avgpool_kernel<<<128, 224>>>(att_tempo, att_motion, meanfeat);
    gemm_naive<<<(128 * 512 + 255) / 256, 256>>>(meanfeat, Wli, bli, xin_bf + 1280 * 512, 128, 512, 204);

    // both modality GEMMs in one launch (grid.z selects problem)
    gemm_mma<64><<<dim3(16, 10, 2), 256>>>(amot_bf, 1024, Wm_bf, 1024, bm, nullptr, 1, 0,
                                           tmpM, nullptr, 1024, 1024,
                                           atem_bf, Wt_bf, bt, tmpT);
    selfgate_kernel<<<dim3(1280, 2), 256>>>(tmpT, tmpM, embeddings, mminp_bf);

    // mm GEMM needs Wmm_bf from s2
    cudaStreamWaitEvent(0, evW, 0);
    gemm_mma<64><<<dim3(8, 10), 256>>>(mminp_bf, 2560, Wmm_bf, 2560, bmm, nullptr, 1, 0,
                                       nullptr, xin_bf, 512, 2560);
    gemm_mma<64><<<dim3(32, 11), 256>>>(xin_bf, 512, Wih_bf, 512, bsum, nullptr, 1, 0,
                                        xproj, nullptr, 2048, 512);

    cudaMemsetAsync(hA, 0, B_ * H_ * sizeof(float));
    lstm_persistent<<<NBLK_LSTM, 256, lstm_smem>>>(xproj, Whh, act_bf, hA, hB);

    // ---- join, then final projection + log_softmax ----
    cudaStreamWaitEvent(0, evJ, 0);
    gemm_mma<80><<<dim3(125, 10), 256>>>(act_bf, 512, Wo_bf, 512, nullptr, ctxproj, 80, V_,
                                         out, nullptr, 10000, 512);
    logsoftmax_kernel<<<1280, 256, V_ * sizeof(float)>>>(out);
}

// round 16
// speedup vs baseline: 1.0067x; 1.0067x over previous
#include <cuda_runtime.h>
#include <cuda_bf16.h>
#include <math.h>
#include <stdint.h>

// Problem dims
#define B_ 16
#define S_ 80
#define L_ 200
#define E_ 512
#define M_ 1024
#define T_ 1024
#define H_ 512
#define V_ 10000

#define NBLK_LSTM 128

// ---------------- scratch (device globals; no allocation allowed) ----------------
__device__ float g_tmpM[B_ * S_ * M_];
__device__ float g_tmpT[B_ * S_ * T_];
__device__ float g_xproj[(B_ * S_ + B_ * 8) * 4 * H_];
__device__ float g_meanfeat[B_ * 8 * 204];
__device__ float g_bsum[4 * H_];
__device__ float g_hA[B_ * H_];     // h layout: [bg][k][4]  (4 groups x 512 k x 4 batches)
__device__ float g_hB[B_ * H_];
__device__ float g_attw[2 * B_ * L_];
__device__ float g_ctxT[2048 * B_];
__device__ float g_ctxpart[4 * B_ * V_];
__device__ float g_ctxproj[B_ * V_];
__device__ unsigned g_barcnt4[4 * 32];   // per-group barrier counters, 128B apart

// bf16 operands
__device__ __nv_bfloat16 g_amot_bf[B_ * S_ * M_];
__device__ __nv_bfloat16 g_atem_bf[B_ * S_ * T_];
__device__ __nv_bfloat16 g_Wm_bf[M_ * M_];
__device__ __nv_bfloat16 g_Wt_bf[T_ * T_];
__device__ __nv_bfloat16 g_Wmm_bf[H_ * 2560];
__device__ __nv_bfloat16 g_Wih_bf[4 * H_ * H_];
__device__ __nv_bfloat16 g_Wo_bf[V_ * H_];          // Wo[:, 0:512]
__device__ __nv_bfloat16 g_mminp_bf[B_ * S_ * 2560];
__device__ __nv_bfloat16 g_xin_bf[(B_ * S_ + B_ * 8) * H_];
__device__ __nv_bfloat16 g_act_bf[B_ * S_ * H_];

// ---------------- reductions ----------------
__device__ __forceinline__ float warpRedMax(float v) {
    #pragma unroll
    for (int o = 16; o > 0; o >>= 1) v = fmaxf(v, __shfl_xor_sync(0xffffffffu, v, o));
    return v;
}
__device__ __forceinline__ float warpRedSum(float v) {
    #pragma unroll
    for (int o = 16; o > 0; o >>= 1) v += __shfl_xor_sync(0xffffffffu, v, o);
    return v;
}
__device__ __forceinline__ float blockReduceMax(float v, float* red) {
    int w = threadIdx.x >> 5, l = threadIdx.x & 31;
    int nw = (blockDim.x + 31) >> 5;
    v = warpRedMax(v);
    __syncthreads();
    if (l == 0) red[w] = v;
    __syncthreads();
    v = (l < nw) ? red[l] : -1e30f;
    return warpRedMax(v);
}
__device__ __forceinline__ float blockReduceSum(float v, float* red) {
    int w = threadIdx.x >> 5, l = threadIdx.x & 31;
    int nw = (blockDim.x + 31) >> 5;
    v = warpRedSum(v);
    __syncthreads();
    if (l == 0) red[w] = v;
    __syncthreads();
    v = (l < nw) ? red[l] : 0.f;
    return warpRedSum(v);
}

// ---------------- mma.sync bf16 primitive ----------------
__device__ __forceinline__ void mma16816(float* c, const uint32_t* a, uint32_t b0, uint32_t b1)
{
    asm volatile(
        "mma.sync.aligned.m16n8k16.row.col.f32.bf16.bf16.f32 "
        "{%0,%1,%2,%3}, {%4,%5,%6,%7}, {%8,%9}, {%0,%1,%2,%3};"
        : "+f"(c[0]), "+f"(c[1]), "+f"(c[2]), "+f"(c[3])
        : "r"(a[0]), "r"(a[1]), "r"(a[2]), "r"(a[3]), "r"(b0), "r"(b1));
}

// ---------------- HMMA bf16 GEMM: C(MxN) = A(MxK) @ B(NxK)^T ----------------
// Optional second problem via blockIdx.z (same shapes).
template<int NT>
__global__ __launch_bounds__(256) void gemm_mma(
    const __nv_bfloat16* __restrict__ A, int lda,
    const __nv_bfloat16* __restrict__ Bw, int ldb,
    const float* __restrict__ bias,
    const float* __restrict__ rowbias, int rowdiv, int rbstride,
    float* __restrict__ Cf, __nv_bfloat16* __restrict__ Cb, int ldc,
    int K,
    const __nv_bfloat16* A2 = nullptr, const __nv_bfloat16* B2 = nullptr,
    const float* bias2 = nullptr, float* Cf2 = nullptr)
{
    if (blockIdx.z == 1) { A = A2; Bw = B2; bias = bias2; Cf = Cf2; Cb = nullptr; }
    constexpr int NWT = NT / 16;
    constexpr int BUI4 = NT * 4;
    __shared__ __nv_bfloat16 sa[2][128 * 40];
    __shared__ __nv_bfloat16 sb[2][NT * 40];

    const int tid = threadIdx.x;
    const int warp = tid >> 5, lane = tid & 31;
    const int wm = warp & 3, wn = warp >> 2;
    const int gid = lane >> 2, tig = lane & 3;
    const int row0 = blockIdx.y * 128;
    const int col0 = blockIdx.x * NT;

    float acc[2][NWT][4];
    #pragma unroll
    for (int mt = 0; mt < 2; mt++)
        #pragma unroll
        for (int nt = 0; nt < NWT; nt++)
            #pragma unroll
            for (int i = 0; i < 4; i++) acc[mt][nt][i] = 0.f;

    const int nch = K >> 5;

    {
        #pragma unroll
        for (int u = 0; u < 2; u++) {
            int idx = tid + u * 256;
            int r = idx >> 2, c4 = idx & 3;
            uint4 v = *(const uint4*)(A + (size_t)(row0 + r) * lda + c4 * 8);
            *(uint4*)(&sa[0][r * 40 + c4 * 8]) = v;
        }
        #pragma unroll
        for (int u = 0; u < (BUI4 + 255) / 256; u++) {
            int idx = tid + u * 256;
            if (idx < BUI4) {
                int r = idx >> 2, c4 = idx & 3;
                uint4 v = *(const uint4*)(Bw + (size_t)(col0 + r) * ldb + c4 * 8);
                *(uint4*)(&sb[0][r * 40 + c4 * 8]) = v;
            }
        }
    }
    __syncthreads();

    for (int ch = 0; ch < nch; ch++) {
        uint4 pa[2], pb[(BUI4 + 255) / 256];
        const bool more = (ch + 1) < nch;
        if (more) {
            const int k0 = (ch + 1) << 5;
            #pragma unroll
            for (int u = 0; u < 2; u++) {
                int idx = tid + u * 256;
                int r = idx >> 2, c4 = idx & 3;
                pa[u] = *(const uint4*)(A + (size_t)(row0 + r) * lda + k0 + c4 * 8);
            }
            #pragma unroll
            for (int u = 0; u < (BUI4 + 255) / 256; u++) {
                int idx = tid + u * 256;
                if (idx < BUI4) {
                    int r = idx >> 2, c4 = idx & 3;
                    pb[u] = *(const uint4*)(Bw + (size_t)(col0 + r) * ldb + k0 + c4 * 8);
                }
            }
        }

        const __nv_bfloat16* sA = sa[ch & 1];
        const __nv_bfloat16* sB = sb[ch & 1];
        #pragma unroll
        for (int s = 0; s < 2; s++) {
            uint32_t af[2][4];
            #pragma unroll
            for (int mt = 0; mt < 2; mt++) {
                const __nv_bfloat16* p = sA + (wm * 32 + mt * 16 + gid) * 40 + s * 16 + 2 * tig;
                af[mt][0] = *(const uint32_t*)(p);
                af[mt][1] = *(const uint32_t*)(p + 8 * 40);
                af[mt][2] = *(const uint32_t*)(p + 8);
                af[mt][3] = *(const uint32_t*)(p + 8 * 40 + 8);
            }
            #pragma unroll
            for (int nt = 0; nt < NWT; nt++) {
                const __nv_bfloat16* p = sB + (wn * (NT / 2) + nt * 8 + gid) * 40 + s * 16 + 2 * tig;
                uint32_t b0 = *(const uint32_t*)(p);
                uint32_t b1 = *(const uint32_t*)(p + 8);
                mma16816(acc[0][nt], af[0], b0, b1);
                mma16816(acc[1][nt], af[1], b0, b1);
            }
        }

        if (more) {
            __nv_bfloat16* dA = sa[(ch + 1) & 1];
            __nv_bfloat16* dB = sb[(ch + 1) & 1];
            #pragma unroll
            for (int u = 0; u < 2; u++) {
                int idx = tid + u * 256;
                int r = idx >> 2, c4 = idx & 3;
                *(uint4*)(&dA[r * 40 + c4 * 8]) = pa[u];
            }
            #pragma unroll
            for (int u = 0; u < (BUI4 + 255) / 256; u++) {
                int idx = tid + u * 256;
                if (idx < BUI4) {
                    int r = idx >> 2, c4 = idx & 3;
                    *(uint4*)(&dB[r * 40 + c4 * 8]) = pb[u];
                }
            }
        }
        __syncthreads();
    }

    #pragma unroll
    for (int mt = 0; mt < 2; mt++) {
        #pragma unroll
        for (int half = 0; half < 2; half++) {
            int r = row0 + wm * 32 + mt * 16 + gid + half * 8;
            const float* rbp = rowbias ? (rowbias + (size_t)(r / rowdiv) * rbstride) : nullptr;
            #pragma unroll
            for (int nt = 0; nt < NWT; nt++) {
                int c = col0 + wn * (NT / 2) + nt * 8 + 2 * tig;
                float v0 = acc[mt][nt][half * 2 + 0];
                float v1 = acc[mt][nt][half * 2 + 1];
                if (bias) { v0 += bias[c]; v1 += bias[c + 1]; }
                if (rbp)  { v0 += rbp[c];  v1 += rbp[c + 1];  }
                if (Cf) *(float2*)(Cf + (size_t)r * ldc + c) = make_float2(v0, v1);
                if (Cb) {
                    __nv_bfloat162 p = __floats2bfloat162_rn(v0, v1);
                    *(__nv_bfloat162*)(Cb + (size_t)r * ldc + c) = p;
                }
            }
        }
    }
}

// ---------------- merged fp32 -> bf16 conversion (all six main-path buffers, one launch) ----------------
#define F2B_N0 327680                       // amot  1280*1024/4
#define F2B_N1 (F2B_N0 + 327680)            // atem
#define F2B_N2 (F2B_N1 + 262144)            // Wm    1024*1024/4
#define F2B_N3 (F2B_N2 + 262144)            // Wt
#define F2B_N4 (F2B_N3 + 327680)            // Wmm   512*2560/4
#define F2B_N5 (F2B_N4 + 262144)            // Wih   2048*512/4

__global__ void f2b_all_kernel(
    const float* __restrict__ s0, __nv_bfloat16* __restrict__ d0,
    const float* __restrict__ s1, __nv_bfloat16* __restrict__ d1,
    const float* __restrict__ s2p, __nv_bfloat16* __restrict__ d2,
    const float* __restrict__ s3, __nv_bfloat16* __restrict__ d3,
    const float* __restrict__ s4, __nv_bfloat16* __restrict__ d4,
    const float* __restrict__ s5, __nv_bfloat16* __restrict__ d5)
{
    int i = blockIdx.x * blockDim.x + threadIdx.x;
    const float* s; __nv_bfloat16* d; int off;
    if      (i < F2B_N0) { s = s0;  d = d0; off = 0; }
    else if (i < F2B_N1) { s = s1;  d = d1; off = F2B_N0; }
    else if (i < F2B_N2) { s = s2p; d = d2; off = F2B_N1; }
    else if (i < F2B_N3) { s = s3;  d = d3; off = F2B_N2; }
    else if (i < F2B_N4) { s = s4;  d = d4; off = F2B_N3; }
    else if (i < F2B_N5) { s = s5;  d = d5; off = F2B_N4; }
    else return;
    int j = i - off;
    float4 v = ((const float4*)s)[j];
    __nv_bfloat162 p0 = __floats2bfloat162_rn(v.x, v.y);
    __nv_bfloat162 p1 = __floats2bfloat162_rn(v.z, v.w);
    ((uint2*)d)[j] = make_uint2(*(uint32_t*)&p0, *(uint32_t*)&p1);
}

// Wo[:, 0:512] strided slice -> bf16 (rows V_, src stride 2560)
__global__ void f2b_wo_kernel(const float* __restrict__ s, __nv_bfloat16* __restrict__ d)
{
    int i = blockIdx.x * blockDim.x + threadIdx.x;
    if (i >= V_ * 128) return;
    int r = i >> 7, c4 = i & 127;
    float4 v = ((const float4*)(s + (size_t)r * 2560))[c4];
    __nv_bfloat162 p0 = __floats2bfloat162_rn(v.x, v.y);
    __nv_bfloat162 p1 = __floats2bfloat162_rn(v.z, v.w);
    ((uint2*)(d + (size_t)r * 512))[c4] = make_uint2(*(uint32_t*)&p0, *(uint32_t*)&p1);
}

// ---------------- self-gating (fused both modalities via grid.y) ----------------
__global__ __launch_bounds__(256) void selfgate_kernel(const float* __restrict__ XT,
                                                       const float* __restrict__ XM,
                                                       __nv_bfloat16* __restrict__ out)
{
    __shared__ float red[32];
    int row = blockIdx.x;
    const float* x = (blockIdx.y == 0 ? XT : XM) + (size_t)row * 1024;
    int colOff = blockIdx.y == 0 ? 512 : 1536;
    float xv[4];
    float m = -1e30f;
    #pragma unroll
    for (int i = 0; i < 4; i++) { xv[i] = x[threadIdx.x + i * 256]; m = fmaxf(m, xv[i]); }
    m = blockReduceMax(m, red);
    float ev[4];
    float s = 0.f;
    #pragma unroll
    for (int i = 0; i < 4; i++) { ev[i] = expf(xv[i] - m); s += ev[i]; }
    s = blockReduceSum(s, red);
    float inv = 1.f / s;
    __nv_bfloat16* o = out + (size_t)row * 2560 + colOff;
    #pragma unroll
    for (int i = 0; i < 4; i++) o[threadIdx.x + i * 256] = __float2bfloat16(xv[i] * ev[i] * inv);
}

__global__ void copy_emb(const float* __restrict__ emb, __nv_bfloat16* __restrict__ mm_inp)
{
    int idx = blockIdx.x * blockDim.x + threadIdx.x;
    if (idx >= 1280 * 128) return;
    int row = idx >> 7, c4 = idx & 127;
    float4 v = ((const float4*)(emb + (size_t)row * 512))[c4];
    __nv_bfloat162 p0 = __floats2bfloat162_rn(v.x, v.y);
    __nv_bfloat162 p1 = __floats2bfloat162_rn(v.z, v.w);
    ((uint2*)(mm_inp + (size_t)row * 2560))[c4] = make_uint2(*(uint32_t*)&p0, *(uint32_t*)&p1);
}

__global__ void avgpool_kernel(const float* __restrict__ att_tempo,
                               const float* __restrict__ att_motion,
                               float* __restrict__ out)
{
    int c = threadIdx.x;
    if (c >= 204) return;
    int b = blockIdx.x >> 3, s8 = blockIdx.x & 7;
    const float* src = (c < 102) ? att_tempo : att_motion;
    int cc = (c < 102) ? c : c - 102;
    const float* base = src + ((size_t)(b * 80 + s8 * 10)) * 1024 + cc * 10;
    float s = 0.f;
    #pragma unroll
    for (int r = 0; r < 10; r++) {
        const float* p = base + r * 1024;
        #pragma unroll
        for (int q = 0; q < 10; q++) s += p[q];
    }
    out[(size_t)blockIdx.x * 204 + c] = s * 0.01f;
}

__global__ void gemm_naive(const float* __restrict__ A, const float* __restrict__ Bm,
                           const float* __restrict__ bias, __nv_bfloat16* __restrict__ C,
                           int M, int N, int K)
{
    int idx = blockIdx.x * blockDim.x + threadIdx.x;
    if (idx >= M * N) return;
    int m = idx / N, n = idx % N;
    const float* a = A + (size_t)m * K;
    const float* b = Bm + (size_t)n * K;
    float s = 0.f;
    for (int k = 0; k < K; k++) s += a[k] * b[k];
    C[idx] = __float2bfloat16(s + bias[n]);
}

__global__ void bsum_kernel(const float* __restrict__ a, const float* __restrict__ b,
                            float* __restrict__ o)
{
    int i = blockIdx.x * blockDim.x + threadIdx.x;
    if (i < 2048) o[i] = a[i] + b[i];
}

// ---------------- persistent LSTM v2: 32 unit-groups x 4 independent batch-groups ----------------
__device__ __forceinline__ void group_sync(int bg)
{
    __threadfence();
    __syncthreads();
    if (threadIdx.x == 0) {
        unsigned* cnt = &g_barcnt4[bg * 32];
        unsigned a = atomicAdd(cnt, 1u);
        unsigned target = (a / 32u + 1u) * 32u;
        while (true) {
            unsigned v = *(volatile unsigned*)cnt;
            if ((v - target) < 0x80000000u) break;
        }
    }
    __syncthreads();
}

// smem (floats): Wsh 512*68 = 34816 | hsh 512*4 = 2048 | red 256*17 = 4352 | gsh 256 | csh 64
#define LSTM_SMEMF (34816 + 2048 + 4352 + 256 + 64)

__global__ __launch_bounds__(256) void lstm_persistent(
    const float* __restrict__ xp,
    const float* __restrict__ Whh,
    __nv_bfloat16* __restrict__ act,
    float* __restrict__ hA, float* __restrict__ hB)
{
    extern __shared__ float sm[];
    float* Wsh = sm;                 // [k][64] stride 68, row r = u*4 + gate
    float* hsh = Wsh + 34816;        // [k][4]
    float* red = hsh + 2048;         // 256 outputs x 17
    float* gsh = red + 4352;         // 256
    float* csh = gsh + 256;          // 64 (16 units x 4 batches)

    const int bi = blockIdx.x;
    const int bg = bi & 3;           // batch group 0..3
    const int ug = bi >> 2;          // unit group 0..31
    const int t = threadIdx.x;

    for (int i = t; i < 64 * 512; i += 256) {
        int r = i >> 9, k = i & 511;
        int u = r >> 2, gate = r & 3;
        Wsh[k * 68 + r] = Whh[(size_t)(gate * 512 + ug * 16 + u) * 512 + k];
    }
    if (t < 64) csh[t] = 0.f;
    __syncthreads();

    const int kp = t & 15, tile = t >> 4;      // dot: row tile (4 rows), 16-way k split
    const int rowr = t >> 2, bl = t & 3;       // reduce: output (row, batch)
    const int ur = rowr >> 2, gater = rowr & 3;
    const size_t xp_col = (size_t)(gater * 512 + ug * 16 + ur);
    const int b_global = bg * 4 + bl;
    const int hbase = bg * 2048;
    float* hb[2] = { hA, hB };

    for (int step = 0; step < 88; step++) {
        const float* hin = hb[step & 1];
        float* hout = hb[1 - (step & 1)];

        // prefetch this step's input-projection value early (off the critical chain)
        int rowidx = (step < 8) ? (1280 + b_global * 8 + step) : (b_global * 80 + (step - 8));
        float xv = __ldg(xp + (size_t)rowidx * 2048 + xp_col);

        // stage this group's h: contiguous 2KB = 512 float4
        for (int i = t; i < 512; i += 256) {
            float4 v = __ldcg(((const float4*)(hin + hbase)) + i);
            *(float4*)&hsh[i * 4] = v;
        }
        __syncthreads();

        // 4 rows x 4 batches tile over 32 strided k
        float acc[4][4];
        #pragma unroll
        for (int i = 0; i < 4; i++)
            #pragma unroll
            for (int j = 0; j < 4; j++) acc[i][j] = 0.f;
        const float* wp = Wsh + kp * 68 + tile * 4;
        const float* hp = hsh + kp * 4;
        #pragma unroll
        for (int it = 0; it < 32; it++) {
            float4 wv = *(const float4*)(wp + it * (16 * 68));
            float4 hv = *(const float4*)(hp + it * (16 * 4));
            acc[0][0] += wv.x * hv.x; acc[0][1] += wv.x * hv.y; acc[0][2] += wv.x * hv.z; acc[0][3] += wv.x * hv.w;
            acc[1][0] += wv.y * hv.x; acc[1][1] += wv.y * hv.y; acc[1][2] += wv.y * hv.z; acc[1][3] += wv.y * hv.w;
            acc[2][0] += wv.z * hv.x; acc[2][1] += wv.z * hv.y; acc[2][2] += wv.z * hv.z; acc[2][3] += wv.z * hv.w;
            acc[3][0] += wv.w * hv.x; acc[3][1] += wv.w * hv.y; acc[3][2] += wv.w * hv.z; acc[3][3] += wv.w * hv.w;
        }
        #pragma unroll
        for (int i = 0; i < 4; i++)
            #pragma unroll
            for (int j = 0; j < 4; j++)
                red[((tile * 4 + i) * 4 + j) * 17 + kp] = acc[i][j];
        __syncthreads();

        // reduce 16 partials + add input projection
        {
            float s = 0.f;
            #pragma unroll
            for (int k2 = 0; k2 < 16; k2++) s += red[t * 17 + k2];
            gsh[t] = s + xv;
        }
        __syncthreads();

        if (t < 64) {
            int u = t >> 2, b = t & 3;
            float iv = gsh[(u * 4 + 0) * 4 + b];
            float fv = gsh[(u * 4 + 1) * 4 + b];
            float gv = gsh[(u * 4 + 2) * 4 + b];
            float ov = gsh[(u * 4 + 3) * 4 + b];
            float c = csh[t];
            float ig = 1.f / (1.f + expf(-iv));
            float fg = 1.f / (1.f + expf(-fv));
            float og = 1.f / (1.f + expf(-ov));
            float cn = fg * c + ig * tanhf(gv);
            float hn = og * tanhf(cn);
            csh[t] = cn;
            int ku = ug * 16 + u;
            hout[hbase + ku * 4 + b] = hn;
            if (step >= 8)
                act[(size_t)((bg * 4 + b) * 80 + step - 8) * 512 + ku] = __float2bfloat16(tanhf(hn));
        }
        group_sync(bg);
    }
}

// ---------------- attention scores (both modalities via grid.y) ----------------
__global__ __launch_bounds__(256) void attn_scores(
    const float* __restrict__ tf, const float* __restrict__ mf,
    const float* __restrict__ wst, const float* __restrict__ wsm,
    const int* __restrict__ tlens, const int* __restrict__ mlens,
    float* __restrict__ wout)
{
    __shared__ float sf[200];
    __shared__ float red[32];
    int b = blockIdx.x;
    const float* feat = blockIdx.y == 0 ? tf : mf;
    const float* wf = blockIdx.y == 0 ? wst : wsm;
    const int* lens = blockIdx.y == 0 ? tlens : mlens;
    float* wo = wout + blockIdx.y * 16 * 200;
    int tid = threadIdx.x, warp = tid >> 5, lane = tid & 31;
    const float* fb = feat + (size_t)b * 200 * 1024;

    for (int l = warp; l < 200; l += 8) {
        const float* fr = fb + (size_t)l * 1024;
        float s = 0.f;
        for (int k = lane; k < 1024; k += 32) s += fr[k] * wf[k];
        s = warpRedSum(s);
        if (lane == 0) sf[l] = s;
    }
    __syncthreads();
    int len = lens[b];
    float m = -1e30f;
    for (int l = tid; l < len; l += 256) m = fmaxf(m, sf[l]);
    m = blockReduceMax(m, red);
    float s = 0.f;
    for (int l = tid; l < len; l += 256) s += expf(sf[l] - m);
    s = blockReduceSum(s, red);
    float inv = 1.f / s;
    __syncthreads();
    for (int l = tid; l < 200; l += 256)
        wo[b * 200 + l] = (l < len) ? expf(sf[l] - m) * inv : 0.f;
}

// ---------------- attention context gather (both modalities via grid.z) ----------------
__global__ __launch_bounds__(128) void attn_ctx(
    const float* __restrict__ tf, const float* __restrict__ mf,
    const float* __restrict__ w, float* __restrict__ ctxT)
{
    __shared__ float ws[200];
    int b = blockIdx.x;
    int f = blockIdx.y * 128 + threadIdx.x;
    const float* feat = blockIdx.z == 0 ? tf : mf;
    const float* wp = w + blockIdx.z * 16 * 200;
    int off = blockIdx.z * 1024;
    for (int l = threadIdx.x; l < 200; l += 128) ws[l] = wp[b * 200 + l];
    __syncthreads();
    const float* fb = feat + (size_t)b * 200 * 1024 + f;
    float acc = 0.f;
    #pragma unroll 4
    for (int l = 0; l < 200; l++) acc += ws[l] * fb[(size_t)l * 1024];
    ctxT[(size_t)(off + f) * 16 + b] = acc;
}

// ---------------- ctxproj split-k: Cp[kc][b][v] = partial dot over 512-k chunk ----------------
__global__ __launch_bounds__(64) void ctxproj_part(
    const float* __restrict__ AT, const float* __restrict__ Wo,
    float* __restrict__ Cp)
{
    int tid = threadIdx.x;
    int bq = tid & 3, vl = tid >> 2;
    int v = blockIdx.x * 16 + vl;
    int kc = blockIdx.y;                       // 0..3
    const float4* w4 = (const float4*)(Wo + (size_t)v * 2560 + 512 + kc * 512);
    const float4* a4 = (const float4*)(AT + (size_t)kc * 512 * 16);
    float a0 = 0.f, a1 = 0.f, a2 = 0.f, a3 = 0.f;
    #pragma unroll 4
    for (int k4 = 0; k4 < 128; k4++) {
        float4 w = w4[k4];
        float4 x0 = a4[(k4 * 4 + 0) * 4 + bq];
        float4 x1 = a4[(k4 * 4 + 1) * 4 + bq];
        float4 x2 = a4[(k4 * 4 + 2) * 4 + bq];
        float4 x3 = a4[(k4 * 4 + 3) * 4 + bq];
        a0 += w.x * x0.x + w.y * x1.x + w.z * x2.x + w.w * x3.x;
        a1 += w.x * x0.y + w.y * x1.y + w.z * x2.y + w.w * x3.y;
        a2 += w.x * x0.z + w.y * x1.z + w.z * x2.z + w.w * x3.z;
        a3 += w.x * x0.w + w.y * x1.w + w.z * x2.w + w.w * x3.w;
    }
    float* C = Cp + (size_t)kc * 16 * V_;
    C[(size_t)(bq * 4 + 0) * V_ + v] = a0;
    C[(size_t)(bq * 4 + 1) * V_ + v] = a1;
    C[(size_t)(bq * 4 + 2) * V_ + v] = a2;
    C[(size_t)(bq * 4 + 3) * V_ + v] = a3;
}

__global__ void ctxproj_reduce(const float* __restrict__ Cp, const float* __restrict__ bo,
                               float* __restrict__ C)
{
    int i = blockIdx.x * blockDim.x + threadIdx.x;
    if (i >= 16 * V_) return;
    int v = i % V_;
    float s = bo[v];
    #pragma unroll
    for (int kc = 0; kc < 4; kc++) s += Cp[(size_t)kc * 16 * V_ + i];
    C[i] = s;
}

// ---------------- log_softmax over V (in-place) ----------------
__global__ __launch_bounds__(256) void logsoftmax_kernel(float* __restrict__ X)
{
    extern __shared__ float sh[];
    __shared__ float red[32];
    int row = blockIdx.x;
    float* x = X + (size_t)row * V_;
    float m = -1e30f;
    for (int i = threadIdx.x; i < V_; i += 256) { float v = x[i]; sh[i] = v; m = fmaxf(m, v); }
    m = blockReduceMax(m, red);
    float s = 0.f;
    for (int i = threadIdx.x; i < V_; i += 256) s += expf(sh[i] - m);
    s = blockReduceSum(s, red);
    float lse = m + logf(s);
    for (int i = threadIdx.x; i < V_; i += 256) x[i] = sh[i] - lse;
}

// ---------------- host ----------------
extern "C" void kernel_launch(void* const* d_in, const int* in_sizes, int n_in,
                              void* d_out, int out_size)
{
    (void)in_sizes; (void)n_in; (void)out_size;
    const float* mfeat       = (const float*)d_in[0];
    const float* tfeat       = (const float*)d_in[1];
    const float* att_motion  = (const float*)d_in[2];
    const float* att_tempo   = (const float*)d_in[3];
    const float* embeddings  = (const float*)d_in[4];
    const int*   mlens       = (const int*)d_in[5];
    const int*   tlens       = (const int*)d_in[6];
    const float* Wm   = (const float*)d_in[8];
    const float* bm   = (const float*)d_in[9];
    const float* Wt   = (const float*)d_in[10];
    const float* bt   = (const float*)d_in[11];
    const float* Wmm  = (const float*)d_in[12];
    const float* bmm  = (const float*)d_in[13];
    const float* Wli  = (const float*)d_in[14];
    const float* bli  = (const float*)d_in[15];
    const float* Wih  = (const float*)d_in[16];
    const float* Whh  = (const float*)d_in[17];
    const float* bih  = (const float*)d_in[18];
    const float* bhh  = (const float*)d_in[19];
    const float* Wsm  = (const float*)d_in[20];
    const float* Wst  = (const float*)d_in[22];
    const float* Wo   = (const float*)d_in[24];
    const float* bo   = (const float*)d_in[25];
    float* out = (float*)d_out;

    float *tmpM, *tmpT, *xproj, *meanfeat, *bsum, *hA, *hB, *attw, *ctxT, *ctxpart, *ctxproj;
    __nv_bfloat16 *amot_bf, *atem_bf, *Wm_bf, *Wt_bf, *Wmm_bf, *Wih_bf, *Wo_bf;
    __nv_bfloat16 *mminp_bf, *xin_bf, *act_bf;
    cudaGetSymbolAddress((void**)&tmpM, g_tmpM);
    cudaGetSymbolAddress((void**)&tmpT, g_tmpT);
    cudaGetSymbolAddress((void**)&xproj, g_xproj);
    cudaGetSymbolAddress((void**)&meanfeat, g_meanfeat);
    cudaGetSymbolAddress((void**)&bsum, g_bsum);
    cudaGetSymbolAddress((void**)&hA, g_hA);
    cudaGetSymbolAddress((void**)&hB, g_hB);
    cudaGetSymbolAddress((void**)&attw, g_attw);
    cudaGetSymbolAddress((void**)&ctxT, g_ctxT);
    cudaGetSymbolAddress((void**)&ctxpart, g_ctxpart);
    cudaGetSymbolAddress((void**)&ctxproj, g_ctxproj);
    cudaGetSymbolAddress((void**)&amot_bf, g_amot_bf);
    cudaGetSymbolAddress((void**)&atem_bf, g_atem_bf);
    cudaGetSymbolAddress((void**)&Wm_bf, g_Wm_bf);
    cudaGetSymbolAddress((void**)&Wt_bf, g_Wt_bf);
    cudaGetSymbolAddress((void**)&Wmm_bf, g_Wmm_bf);
    cudaGetSymbolAddress((void**)&Wih_bf, g_Wih_bf);
    cudaGetSymbolAddress((void**)&Wo_bf, g_Wo_bf);
    cudaGetSymbolAddress((void**)&mminp_bf, g_mminp_bf);
    cudaGetSymbolAddress((void**)&xin_bf, g_xin_bf);
    cudaGetSymbolAddress((void**)&act_bf, g_act_bf);

    const int lstm_smem = LSTM_SMEMF * (int)sizeof(float);
    cudaFuncSetAttribute(lstm_persistent, cudaFuncAttributeMaxDynamicSharedMemorySize, lstm_smem);

    static cudaStream_t s2 = nullptr;
    static cudaEvent_t evF = nullptr, evJ = nullptr;
    if (!s2) {
        cudaStreamCreateWithFlags(&s2, cudaStreamNonBlocking);
        cudaEventCreateWithFlags(&evF, cudaEventDisableTiming);
        cudaEventCreateWithFlags(&evJ, cudaEventDisableTiming);
    }

    // ---- fork: attention path on s2 (depends only on inputs) ----
    cudaEventRecord(evF, 0);
    cudaStreamWaitEvent(s2, evF, 0);
    f2b_wo_kernel<<<(V_ * 128 + 255) / 256, 256, 0, s2>>>(Wo, Wo_bf);
    attn_scores<<<dim3(16, 2), 256, 0, s2>>>(tfeat, mfeat, Wst + 512, Wsm + 512, tlens, mlens, attw);
    attn_ctx<<<dim3(16, 8, 2), 128, 0, s2>>>(tfeat, mfeat, attw, ctxT);
    ctxproj_part<<<dim3(625, 4), 64, 0, s2>>>(ctxT, Wo, ctxpart);
    ctxproj_reduce<<<(16 * V_ + 255) / 256, 256, 0, s2>>>(ctxpart, bo, ctxproj);
    cudaEventRecord(evJ, s2);

    // ---- main path ----
    f2b_all_kernel<<<(F2B_N5 + 255) / 256, 256>>>(
        att_motion, amot_bf, att_tempo, atem_bf, Wm, Wm_bf,
        Wt, Wt_bf, Wmm, Wmm_bf, Wih, Wih_bf);

    bsum_kernel<<<8, 256>>>(bih, bhh, bsum);
    avgpool_kernel<<<128, 224>>>(att_tempo, att_motion, meanfeat);
    gemm_naive<<<(128 * 512 + 255) / 256, 256>>>(meanfeat, Wli, bli, xin_bf + 1280 * 512, 128, 512, 204);

    // both modality GEMMs in one launch (grid.z selects problem)
    gemm_mma<64><<<dim3(16, 10, 2), 256>>>(amot_bf, 1024, Wm_bf, 1024, bm, nullptr, 1, 0,
                                           tmpM, nullptr, 1024, 1024,
                                           atem_bf, Wt_bf, bt, tmpT);
    selfgate_kernel<<<dim3(1280, 2), 256>>>(tmpT, tmpM, mminp_bf);
    copy_emb<<<640, 256>>>(embeddings, mminp_bf);

    gemm_mma<64><<<dim3(8, 10), 256>>>(mminp_bf, 2560, Wmm_bf, 2560, bmm, nullptr, 1, 0,
                                       nullptr, xin_bf, 512, 2560);
    gemm_mma<64><<<dim3(32, 11), 256>>>(xin_bf, 512, Wih_bf, 512, bsum, nullptr, 1, 0,
                                        xproj, nullptr, 2048, 512);

    cudaMemsetAsync(hA, 0, B_ * H_ * sizeof(float));
    lstm_persistent<<<NBLK_LSTM, 256, lstm_smem>>>(xproj, Whh, act_bf, hA, hB);

    // ---- join, then final projection + log_softmax ----
    cudaStreamWaitEvent(0, evJ, 0);
    gemm_mma<80><<<dim3(125, 10), 256>>>(act_bf, 512, Wo_bf, 512, nullptr, ctxproj, 80, V_,
                                         out, nullptr, 10000, 512);
    logsoftmax_kernel<<<1280, 256, V_ * sizeof(float)>>>(out);
}

// round 17
// speedup vs baseline: 1.1750x; 1.1672x over previous
#include <cuda_runtime.h>
#include <cuda_bf16.h>
#include <math.h>
#include <stdint.h>

// Problem dims
#define B_ 16
#define S_ 80
#define L_ 200
#define E_ 512
#define M_ 1024
#define T_ 1024
#define H_ 512
#define V_ 10000

#define NBLK_LSTM 128

// ---------------- scratch (device globals; no allocation allowed) ----------------
__device__ float g_tmpM[B_ * S_ * M_];
__device__ float g_tmpT[B_ * S_ * T_];
__device__ float g_xproj[(B_ * S_ + B_ * 8) * 4 * H_];
__device__ float g_meanfeat[B_ * 8 * 204];
__device__ float g_bsum[4 * H_];
__device__ float g_attw[2 * B_ * L_];
__device__ float g_ctxT[2048 * B_];
__device__ float g_ctxpart[4 * B_ * V_];
__device__ float g_ctxproj[B_ * V_];
__device__ unsigned g_barcnt4[4 * 32];   // per-group barrier counters, 128B apart

// bf16 operands
__device__ __nv_bfloat16 g_hbA[B_ * H_];   // h (bf16), layout [bg][b(4)][k(512)]
__device__ __nv_bfloat16 g_hbB[B_ * H_];
__device__ __nv_bfloat16 g_amot_bf[B_ * S_ * M_];
__device__ __nv_bfloat16 g_atem_bf[B_ * S_ * T_];
__device__ __nv_bfloat16 g_Wm_bf[M_ * M_];
__device__ __nv_bfloat16 g_Wt_bf[T_ * T_];
__device__ __nv_bfloat16 g_Wmm_bf[H_ * 2560];
__device__ __nv_bfloat16 g_Wih_bf[4 * H_ * H_];
__device__ __nv_bfloat16 g_Wo_bf[V_ * H_];          // Wo[:, 0:512]
__device__ __nv_bfloat16 g_mminp_bf[B_ * S_ * 2560];
__device__ __nv_bfloat16 g_xin_bf[(B_ * S_ + B_ * 8) * H_];
__device__ __nv_bfloat16 g_act_bf[B_ * S_ * H_];

// ---------------- reductions ----------------
__device__ __forceinline__ float warpRedMax(float v) {
    #pragma unroll
    for (int o = 16; o > 0; o >>= 1) v = fmaxf(v, __shfl_xor_sync(0xffffffffu, v, o));
    return v;
}
__device__ __forceinline__ float warpRedSum(float v) {
    #pragma unroll
    for (int o = 16; o > 0; o >>= 1) v += __shfl_xor_sync(0xffffffffu, v, o);
    return v;
}
__device__ __forceinline__ float blockReduceMax(float v, float* red) {
    int w = threadIdx.x >> 5, l = threadIdx.x & 31;
    int nw = (blockDim.x + 31) >> 5;
    v = warpRedMax(v);
    __syncthreads();
    if (l == 0) red[w] = v;
    __syncthreads();
    v = (l < nw) ? red[l] : -1e30f;
    return warpRedMax(v);
}
__device__ __forceinline__ float blockReduceSum(float v, float* red) {
    int w = threadIdx.x >> 5, l = threadIdx.x & 31;
    int nw = (blockDim.x + 31) >> 5;
    v = warpRedSum(v);
    __syncthreads();
    if (l == 0) red[w] = v;
    __syncthreads();
    v = (l < nw) ? red[l] : 0.f;
    return warpRedSum(v);
}

// ---------------- mma.sync bf16 primitive ----------------
__device__ __forceinline__ void mma16816(float* c, const uint32_t* a, uint32_t b0, uint32_t b1)
{
    asm volatile(
        "mma.sync.aligned.m16n8k16.row.col.f32.bf16.bf16.f32 "
        "{%0,%1,%2,%3}, {%4,%5,%6,%7}, {%8,%9}, {%0,%1,%2,%3};"
        : "+f"(c[0]), "+f"(c[1]), "+f"(c[2]), "+f"(c[3])
        : "r"(a[0]), "r"(a[1]), "r"(a[2]), "r"(a[3]), "r"(b0), "r"(b1));
}

// ---------------- HMMA bf16 GEMM: C(MxN) = A(MxK) @ B(NxK)^T ----------------
// Optional second problem via blockIdx.z (same shapes).
template<int NT>
__global__ __launch_bounds__(256) void gemm_mma(
    const __nv_bfloat16* __restrict__ A, int lda,
    const __nv_bfloat16* __restrict__ Bw, int ldb,
    const float* __restrict__ bias,
    const float* __restrict__ rowbias, int rowdiv, int rbstride,
    float* __restrict__ Cf, __nv_bfloat16* __restrict__ Cb, int ldc,
    int K,
    const __nv_bfloat16* A2 = nullptr, const __nv_bfloat16* B2 = nullptr,
    const float* bias2 = nullptr, float* Cf2 = nullptr)
{
    if (blockIdx.z == 1) { A = A2; Bw = B2; bias = bias2; Cf = Cf2; Cb = nullptr; }
    constexpr int NWT = NT / 16;
    constexpr int BUI4 = NT * 4;
    __shared__ __nv_bfloat16 sa[2][128 * 40];
    __shared__ __nv_bfloat16 sb[2][NT * 40];

    const int tid = threadIdx.x;
    const int warp = tid >> 5, lane = tid & 31;
    const int wm = warp & 3, wn = warp >> 2;
    const int gid = lane >> 2, tig = lane & 3;
    const int row0 = blockIdx.y * 128;
    const int col0 = blockIdx.x * NT;

    float acc[2][NWT][4];
    #pragma unroll
    for (int mt = 0; mt < 2; mt++)
        #pragma unroll
        for (int nt = 0; nt < NWT; nt++)
            #pragma unroll
            for (int i = 0; i < 4; i++) acc[mt][nt][i] = 0.f;

    const int nch = K >> 5;

    {
        #pragma unroll
        for (int u = 0; u < 2; u++) {
            int idx = tid + u * 256;
            int r = idx >> 2, c4 = idx & 3;
            uint4 v = *(const uint4*)(A + (size_t)(row0 + r) * lda + c4 * 8);
            *(uint4*)(&sa[0][r * 40 + c4 * 8]) = v;
        }
        #pragma unroll
        for (int u = 0; u < (BUI4 + 255) / 256; u++) {
            int idx = tid + u * 256;
            if (idx < BUI4) {
                int r = idx >> 2, c4 = idx & 3;
                uint4 v = *(const uint4*)(Bw + (size_t)(col0 + r) * ldb + c4 * 8);
                *(uint4*)(&sb[0][r * 40 + c4 * 8]) = v;
            }
        }
    }
    __syncthreads();

    for (int ch = 0; ch < nch; ch++) {
        uint4 pa[2], pb[(BUI4 + 255) / 256];
        const bool more = (ch + 1) < nch;
        if (more) {
            const int k0 = (ch + 1) << 5;
            #pragma unroll
            for (int u = 0; u < 2; u++) {
                int idx = tid + u * 256;
                int r = idx >> 2, c4 = idx & 3;
                pa[u] = *(const uint4*)(A + (size_t)(row0 + r) * lda + k0 + c4 * 8);
            }
            #pragma unroll
            for (int u = 0; u < (BUI4 + 255) / 256; u++) {
                int idx = tid + u * 256;
                if (idx < BUI4) {
                    int r = idx >> 2, c4 = idx & 3;
                    pb[u] = *(const uint4*)(Bw + (size_t)(col0 + r) * ldb + k0 + c4 * 8);
                }
            }
        }

        const __nv_bfloat16* sA = sa[ch & 1];
        const __nv_bfloat16* sB = sb[ch & 1];
        #pragma unroll
        for (int s = 0; s < 2; s++) {
            uint32_t af[2][4];
            #pragma unroll
            for (int mt = 0; mt < 2; mt++) {
                const __nv_bfloat16* p = sA + (wm * 32 + mt * 16 + gid) * 40 + s * 16 + 2 * tig;
                af[mt][0] = *(const uint32_t*)(p);
                af[mt][1] = *(const uint32_t*)(p + 8 * 40);
                af[mt][2] = *(const uint32_t*)(p + 8);
                af[mt][3] = *(const uint32_t*)(p + 8 * 40 + 8);
            }
            #pragma unroll
            for (int nt = 0; nt < NWT; nt++) {
                const __nv_bfloat16* p = sB + (wn * (NT / 2) + nt * 8 + gid) * 40 + s * 16 + 2 * tig;
                uint32_t b0 = *(const uint32_t*)(p);
                uint32_t b1 = *(const uint32_t*)(p + 8);
                mma16816(acc[0][nt], af[0], b0, b1);
                mma16816(acc[1][nt], af[1], b0, b1);
            }
        }

        if (more) {
            __nv_bfloat16* dA = sa[(ch + 1) & 1];
            __nv_bfloat16* dB = sb[(ch + 1) & 1];
            #pragma unroll
            for (int u = 0; u < 2; u++) {
                int idx = tid + u * 256;
                int r = idx >> 2, c4 = idx & 3;
                *(uint4*)(&dA[r * 40 + c4 * 8]) = pa[u];
            }
            #pragma unroll
            for (int u = 0; u < (BUI4 + 255) / 256; u++) {
                int idx = tid + u * 256;
                if (idx < BUI4) {
                    int r = idx >> 2, c4 = idx & 3;
                    *(uint4*)(&dB[r * 40 + c4 * 8]) = pb[u];
                }
            }
        }
        __syncthreads();
    }

    #pragma unroll
    for (int mt = 0; mt < 2; mt++) {
        #pragma unroll
        for (int half = 0; half < 2; half++) {
            int r = row0 + wm * 32 + mt * 16 + gid + half * 8;
            const float* rbp = rowbias ? (rowbias + (size_t)(r / rowdiv) * rbstride) : nullptr;
            #pragma unroll
            for (int nt = 0; nt < NWT; nt++) {
                int c = col0 + wn * (NT / 2) + nt * 8 + 2 * tig;
                float v0 = acc[mt][nt][half * 2 + 0];
                float v1 = acc[mt][nt][half * 2 + 1];
                if (bias) { v0 += bias[c]; v1 += bias[c + 1]; }
                if (rbp)  { v0 += rbp[c];  v1 += rbp[c + 1];  }
                if (Cf) *(float2*)(Cf + (size_t)r * ldc + c) = make_float2(v0, v1);
                if (Cb) {
                    __nv_bfloat162 p = __floats2bfloat162_rn(v0, v1);
                    *(__nv_bfloat162*)(Cb + (size_t)r * ldc + c) = p;
                }
            }
        }
    }
}

// ---------------- merged fp32 -> bf16 conversion (all six main-path buffers, one launch) ----------------
#define F2B_N0 327680                       // amot  1280*1024/4
#define F2B_N1 (F2B_N0 + 327680)            // atem
#define F2B_N2 (F2B_N1 + 262144)            // Wm    1024*1024/4
#define F2B_N3 (F2B_N2 + 262144)            // Wt
#define F2B_N4 (F2B_N3 + 327680)            // Wmm   512*2560/4
#define F2B_N5 (F2B_N4 + 262144)            // Wih   2048*512/4

__global__ void f2b_all_kernel(
    const float* __restrict__ s0, __nv_bfloat16* __restrict__ d0,
    const float* __restrict__ s1, __nv_bfloat16* __restrict__ d1,
    const float* __restrict__ s2p, __nv_bfloat16* __restrict__ d2,
    const float* __restrict__ s3, __nv_bfloat16* __restrict__ d3,
    const float* __restrict__ s4, __nv_bfloat16* __restrict__ d4,
    const float* __restrict__ s5, __nv_bfloat16* __restrict__ d5)
{
    int i = blockIdx.x * blockDim.x + threadIdx.x;
    const float* s; __nv_bfloat16* d; int off;
    if      (i < F2B_N0) { s = s0;  d = d0; off = 0; }
    else if (i < F2B_N1) { s = s1;  d = d1; off = F2B_N0; }
    else if (i < F2B_N2) { s = s2p; d = d2; off = F2B_N1; }
    else if (i < F2B_N3) { s = s3;  d = d3; off = F2B_N2; }
    else if (i < F2B_N4) { s = s4;  d = d4; off = F2B_N3; }
    else if (i < F2B_N5) { s = s5;  d = d5; off = F2B_N4; }
    else return;
    int j = i - off;
    float4 v = ((const float4*)s)[j];
    __nv_bfloat162 p0 = __floats2bfloat162_rn(v.x, v.y);
    __nv_bfloat162 p1 = __floats2bfloat162_rn(v.z, v.w);
    ((uint2*)d)[j] = make_uint2(*(uint32_t*)&p0, *(uint32_t*)&p1);
}

// Wo[:, 0:512] strided slice -> bf16 (rows V_, src stride 2560)
__global__ void f2b_wo_kernel(const float* __restrict__ s, __nv_bfloat16* __restrict__ d)
{
    int i = blockIdx.x * blockDim.x + threadIdx.x;
    if (i >= V_ * 128) return;
    int r = i >> 7, c4 = i & 127;
    float4 v = ((const float4*)(s + (size_t)r * 2560))[c4];
    __nv_bfloat162 p0 = __floats2bfloat162_rn(v.x, v.y);
    __nv_bfloat162 p1 = __floats2bfloat162_rn(v.z, v.w);
    ((uint2*)(d + (size_t)r * 512))[c4] = make_uint2(*(uint32_t*)&p0, *(uint32_t*)&p1);
}

// ---------------- self-gating (fused both modalities via grid.y) ----------------
__global__ __launch_bounds__(256) void selfgate_kernel(const float* __restrict__ XT,
                                                       const float* __restrict__ XM,
                                                       __nv_bfloat16* __restrict__ out)
{
    __shared__ float red[32];
    int row = blockIdx.x;
    const float* x = (blockIdx.y == 0 ? XT : XM) + (size_t)row * 1024;
    int colOff = blockIdx.y == 0 ? 512 : 1536;
    float xv[4];
    float m = -1e30f;
    #pragma unroll
    for (int i = 0; i < 4; i++) { xv[i] = x[threadIdx.x + i * 256]; m = fmaxf(m, xv[i]); }
    m = blockReduceMax(m, red);
    float ev[4];
    float s = 0.f;
    #pragma unroll
    for (int i = 0; i < 4; i++) { ev[i] = expf(xv[i] - m); s += ev[i]; }
    s = blockReduceSum(s, red);
    float inv = 1.f / s;
    __nv_bfloat16* o = out + (size_t)row * 2560 + colOff;
    #pragma unroll
    for (int i = 0; i < 4; i++) o[threadIdx.x + i * 256] = __float2bfloat16(xv[i] * ev[i] * inv);
}

__global__ void copy_emb(const float* __restrict__ emb, __nv_bfloat16* __restrict__ mm_inp)
{
    int idx = blockIdx.x * blockDim.x + threadIdx.x;
    if (idx >= 1280 * 128) return;
    int row = idx >> 7, c4 = idx & 127;
    float4 v = ((const float4*)(emb + (size_t)row * 512))[c4];
    __nv_bfloat162 p0 = __floats2bfloat162_rn(v.x, v.y);
    __nv_bfloat162 p1 = __floats2bfloat162_rn(v.z, v.w);
    ((uint2*)(mm_inp + (size_t)row * 2560))[c4] = make_uint2(*(uint32_t*)&p0, *(uint32_t*)&p1);
}

__global__ void avgpool_kernel(const float* __restrict__ att_tempo,
                               const float* __restrict__ att_motion,
                               float* __restrict__ out)
{
    int c = threadIdx.x;
    if (c >= 204) return;
    int b = blockIdx.x >> 3, s8 = blockIdx.x & 7;
    const float* src = (c < 102) ? att_tempo : att_motion;
    int cc = (c < 102) ? c : c - 102;
    const float* base = src + ((size_t)(b * 80 + s8 * 10)) * 1024 + cc * 10;
    float s = 0.f;
    #pragma unroll
    for (int r = 0; r < 10; r++) {
        const float* p = base + r * 1024;
        #pragma unroll
        for (int q = 0; q < 10; q++) s += p[q];
    }
    out[(size_t)blockIdx.x * 204 + c] = s * 0.01f;
}

__global__ void gemm_naive(const float* __restrict__ A, const float* __restrict__ Bm,
                           const float* __restrict__ bias, __nv_bfloat16* __restrict__ C,
                           int M, int N, int K)
{
    int idx = blockIdx.x * blockDim.x + threadIdx.x;
    if (idx >= M * N) return;
    int m = idx / N, n = idx % N;
    const float* a = A + (size_t)m * K;
    const float* b = Bm + (size_t)n * K;
    float s = 0.f;
    for (int k = 0; k < K; k++) s += a[k] * b[k];
    C[idx] = __float2bfloat16(s + bias[n]);
}

__global__ void bsum_kernel(const float* __restrict__ a, const float* __restrict__ b,
                            float* __restrict__ o)
{
    int i = blockIdx.x * blockDim.x + threadIdx.x;
    if (i < 2048) o[i] = a[i] + b[i];
}

// ---------------- persistent LSTM v3: HMMA recurrent dot ----------------
// Block (ug, bg) owns 16 units x 4 batches. 64 gate-rows x 512 k x 4 batches per step
// computed with mma.m16n8k16 (bf16 W and h in smem, fp32 accum). 8 warps =
// 4 m-tiles x 2 k-halves, 16 mma each, 2-way partial reduce. Barrier scope = 32 blocks.
__device__ __forceinline__ void group_sync(int bg)
{
    __threadfence();
    __syncthreads();
    if (threadIdx.x == 0) {
        unsigned* cnt = &g_barcnt4[bg * 32];
        unsigned a = atomicAdd(cnt, 1u);
        unsigned target = (a / 32u + 1u) * 32u;
        while (true) {
            unsigned v = *(volatile unsigned*)cnt;
            if ((v - target) < 0x80000000u) break;
        }
    }
    __syncthreads();
}

// smem bytes: Wsh 64*520*2 = 66560 | hsh 8*520*2 = 8320 | red 512*4 | gsh 256*4 | csh 64*4
#define LSTM_SMEMB (66560 + 8320 + 2048 + 1024 + 256)

__global__ __launch_bounds__(256) void lstm_persistent(
    const float* __restrict__ xp,
    const float* __restrict__ Whh,
    __nv_bfloat16* __restrict__ act,
    __nv_bfloat16* __restrict__ hA, __nv_bfloat16* __restrict__ hB)
{
    extern __shared__ char smraw[];
    __nv_bfloat16* Wsh = (__nv_bfloat16*)smraw;              // [64][520] row r = u*4+gate
    __nv_bfloat16* hsh = (__nv_bfloat16*)(smraw + 66560);    // [8][520]  rows 0..3 = batches
    float* red = (float*)(smraw + 66560 + 8320);             // [2][64][4]
    float* gsh = red + 512;                                  // [64][4]
    float* csh = gsh + 256;                                  // [64]

    const int bi = blockIdx.x;
    const int bg = bi & 3;           // batch group
    const int ug = bi >> 2;          // unit group
    const int t = threadIdx.x;
    const int warp = t >> 5, lane = t & 31;
    const int gid = lane >> 2, tig = lane & 3;
    const int mt = warp & 3, kh = warp >> 2;

    // cache W slice (convert fp32 -> bf16): Wsh[r][k], W row = gate*512 + ug*16 + u
    for (int i = t; i < 8192; i += 256) {
        int r = i >> 7, k4 = i & 127;
        int u = r >> 2, gate = r & 3;
        float4 v = *(const float4*)(Whh + (size_t)(gate * 512 + ug * 16 + u) * 512 + k4 * 4);
        __nv_bfloat162 p0 = __floats2bfloat162_rn(v.x, v.y);
        __nv_bfloat162 p1 = __floats2bfloat162_rn(v.z, v.w);
        *(uint2*)(&Wsh[r * 520 + k4 * 4]) = make_uint2(*(uint32_t*)&p0, *(uint32_t*)&p1);
    }
    // zero hsh (rows 4..7 remain zero forever -> pad batches)
    for (int i = t; i < 2080; i += 256) ((uint32_t*)hsh)[i] = 0;
    if (t < 64) csh[t] = 0.f;
    __syncthreads();

    const int rowr = t >> 2, bl = t & 3;
    const int ur = rowr >> 2, gater = rowr & 3;
    const size_t xp_col = (size_t)(gater * 512 + ug * 16 + ur);
    const int b_global = bg * 4 + bl;
    const int hbase = bg * 2048;                 // bf16 elements
    __nv_bfloat16* hb[2] = { hA, hB };

    const __nv_bfloat16* wbase = Wsh + (mt * 16 + gid) * 520 + kh * 256 + 2 * tig;
    const __nv_bfloat16* hfrag = hsh + gid * 520 + kh * 256 + 2 * tig;

    for (int step = 0; step < 88; step++) {
        const __nv_bfloat16* hin = hb[step & 1] + hbase;
        __nv_bfloat16* hout = hb[1 - (step & 1)] + hbase;

        int rowidx = (step < 8) ? (1280 + b_global * 8 + step) : (b_global * 80 + (step - 8));
        float xv = __ldg(xp + (size_t)rowidx * 2048 + xp_col);

        // stage h rows 0..3: 2048 bf16 = 256 uint4, one per thread
        {
            int n = t >> 6, rest = t & 63;
            uint4 v = __ldcg(((const uint4*)hin) + t);
            *(uint4*)(&hsh[n * 520 + rest * 8]) = v;
        }
        __syncthreads();

        float c0[4] = {0.f, 0.f, 0.f, 0.f};
        #pragma unroll
        for (int kt = 0; kt < 16; kt++) {
            uint32_t af[4];
            af[0] = *(const uint32_t*)(wbase + kt * 16);
            af[1] = *(const uint32_t*)(wbase + 8 * 520 + kt * 16);
            af[2] = *(const uint32_t*)(wbase + kt * 16 + 8);
            af[3] = *(const uint32_t*)(wbase + 8 * 520 + kt * 16 + 8);
            uint32_t b0 = *(const uint32_t*)(hfrag + kt * 16);
            uint32_t b1 = *(const uint32_t*)(hfrag + kt * 16 + 8);
            mma16816(c0, af, b0, b1);
        }
        if (tig < 2) {
            int r0 = mt * 16 + gid;
            float* rp = red + kh * 256;
            rp[r0 * 4 + 2 * tig]           = c0[0];
            rp[r0 * 4 + 2 * tig + 1]       = c0[1];
            rp[(r0 + 8) * 4 + 2 * tig]     = c0[2];
            rp[(r0 + 8) * 4 + 2 * tig + 1] = c0[3];
        }
        __syncthreads();

        gsh[t] = red[t] + red[256 + t] + xv;
        __syncthreads();

        if (t < 64) {
            int u = t >> 2, b = t & 3;
            float iv = gsh[(u * 4 + 0) * 4 + b];
            float fv = gsh[(u * 4 + 1) * 4 + b];
            float gv = gsh[(u * 4 + 2) * 4 + b];
            float ov = gsh[(u * 4 + 3) * 4 + b];
            float c = csh[t];
            float ig = 1.f / (1.f + expf(-iv));
            float fg = 1.f / (1.f + expf(-fv));
            float og = 1.f / (1.f + expf(-ov));
            float cn = fg * c + ig * tanhf(gv);
            float hn = og * tanhf(cn);
            csh[t] = cn;
            int ku = ug * 16 + u;
            hout[b * 512 + ku] = __float2bfloat16(hn);
            if (step >= 8)
                act[(size_t)((bg * 4 + b) * 80 + step - 8) * 512 + ku] = __float2bfloat16(tanhf(hn));
        }
        group_sync(bg);
    }
}

// ---------------- attention scores (both modalities via grid.y) ----------------
__global__ __launch_bounds__(256) void attn_scores(
    const float* __restrict__ tf, const float* __restrict__ mf,
    const float* __restrict__ wst, const float* __restrict__ wsm,
    const int* __restrict__ tlens, const int* __restrict__ mlens,
    float* __restrict__ wout)
{
    __shared__ float sf[200];
    __shared__ float red[32];
    int b = blockIdx.x;
    const float* feat = blockIdx.y == 0 ? tf : mf;
    const float* wf = blockIdx.y == 0 ? wst : wsm;
    const int* lens = blockIdx.y == 0 ? tlens : mlens;
    float* wo = wout + blockIdx.y * 16 * 200;
    int tid = threadIdx.x, warp = tid >> 5, lane = tid & 31;
    const float* fb = feat + (size_t)b * 200 * 1024;

    for (int l = warp; l < 200; l += 8) {
        const float* fr = fb + (size_t)l * 1024;
        float s = 0.f;
        for (int k = lane; k < 1024; k += 32) s += fr[k] * wf[k];
        s = warpRedSum(s);
        if (lane == 0) sf[l] = s;
    }
    __syncthreads();
    int len = lens[b];
    float m = -1e30f;
    for (int l = tid; l < len; l += 256) m = fmaxf(m, sf[l]);
    m = blockReduceMax(m, red);
    float s = 0.f;
    for (int l = tid; l < len; l += 256) s += expf(sf[l] - m);
    s = blockReduceSum(s, red);
    float inv = 1.f / s;
    __syncthreads();
    for (int l = tid; l < 200; l += 256)
        wo[b * 200 + l] = (l < len) ? expf(sf[l] - m) * inv : 0.f;
}

// ---------------- attention context gather (both modalities via grid.z) ----------------
__global__ __launch_bounds__(128) void attn_ctx(
    const float* __restrict__ tf, const float* __restrict__ mf,
    const float* __restrict__ w, float* __restrict__ ctxT)
{
    __shared__ float ws[200];
    int b = blockIdx.x;
    int f = blockIdx.y * 128 + threadIdx.x;
    const float* feat = blockIdx.z == 0 ? tf : mf;
    const float* wp = w + blockIdx.z * 16 * 200;
    int off = blockIdx.z * 1024;
    for (int l = threadIdx.x; l < 200; l += 128) ws[l] = wp[b * 200 + l];
    __syncthreads();
    const float* fb = feat + (size_t)b * 200 * 1024 + f;
    float acc = 0.f;
    #pragma unroll 4
    for (int l = 0; l < 200; l++) acc += ws[l] * fb[(size_t)l * 1024];
    ctxT[(size_t)(off + f) * 16 + b] = acc;
}

// ---------------- ctxproj split-k: Cp[kc][b][v] = partial dot over 512-k chunk ----------------
__global__ __launch_bounds__(64) void ctxproj_part(
    const float* __restrict__ AT, const float* __restrict__ Wo,
    float* __restrict__ Cp)
{
    int tid = threadIdx.x;
    int bq = tid & 3, vl = tid >> 2;
    int v = blockIdx.x * 16 + vl;
    int kc = blockIdx.y;                       // 0..3
    const float4* w4 = (const float4*)(Wo + (size_t)v * 2560 + 512 + kc * 512);
    const float4* a4 = (const float4*)(AT + (size_t)kc * 512 * 16);
    float a0 = 0.f, a1 = 0.f, a2 = 0.f, a3 = 0.f;
    #pragma unroll 4
    for (int k4 = 0; k4 < 128; k4++) {
        float4 w = w4[k4];
        float4 x0 = a4[(k4 * 4 + 0) * 4 + bq];
        float4 x1 = a4[(k4 * 4 + 1) * 4 + bq];
        float4 x2 = a4[(k4 * 4 + 2) * 4 + bq];
        float4 x3 = a4[(k4 * 4 + 3) * 4 + bq];
        a0 += w.x * x0.x + w.y * x1.x + w.z * x2.x + w.w * x3.x;
        a1 += w.x * x0.y + w.y * x1.y + w.z * x2.y + w.w * x3.y;
        a2 += w.x * x0.z + w.y * x1.z + w.z * x2.z + w.w * x3.z;
        a3 += w.x * x0.w + w.y * x1.w + w.z * x2.w + w.w * x3.w;
    }
    float* C = Cp + (size_t)kc * 16 * V_;
    C[(size_t)(bq * 4 + 0) * V_ + v] = a0;
    C[(size_t)(bq * 4 + 1) * V_ + v] = a1;
    C[(size_t)(bq * 4 + 2) * V_ + v] = a2;
    C[(size_t)(bq * 4 + 3) * V_ + v] = a3;
}

__global__ void ctxproj_reduce(const float* __restrict__ Cp, const float* __restrict__ bo,
                               float* __restrict__ C)
{
    int i = blockIdx.x * blockDim.x + threadIdx.x;
    if (i >= 16 * V_) return;
    int v = i % V_;
    float s = bo[v];
    #pragma unroll
    for (int kc = 0; kc < 4; kc++) s += Cp[(size_t)kc * 16 * V_ + i];
    C[i] = s;
}

// ---------------- log_softmax over V (in-place) ----------------
__global__ __launch_bounds__(256) void logsoftmax_kernel(float* __restrict__ X)
{
    extern __shared__ float sh[];
    __shared__ float red[32];
    int row = blockIdx.x;
    float* x = X + (size_t)row * V_;
    float m = -1e30f;
    for (int i = threadIdx.x; i < V_; i += 256) { float v = x[i]; sh[i] = v; m = fmaxf(m, v); }
    m = blockReduceMax(m, red);
    float s = 0.f;
    for (int i = threadIdx.x; i < V_; i += 256) s += expf(sh[i] - m);
    s = blockReduceSum(s, red);
    float lse = m + logf(s);
    for (int i = threadIdx.x; i < V_; i += 256) x[i] = sh[i] - lse;
}

// ---------------- host ----------------
extern "C" void kernel_launch(void* const* d_in, const int* in_sizes, int n_in,
                              void* d_out, int out_size)
{
    (void)in_sizes; (void)n_in; (void)out_size;
    const float* mfeat       = (const float*)d_in[0];
    const float* tfeat       = (const float*)d_in[1];
    const float* att_motion  = (const float*)d_in[2];
    const float* att_tempo   = (const float*)d_in[3];
    const float* embeddings  = (const float*)d_in[4];
    const int*   mlens       = (const int*)d_in[5];
    const int*   tlens       = (const int*)d_in[6];
    const float* Wm   = (const float*)d_in[8];
    const float* bm   = (const float*)d_in[9];
    const float* Wt   = (const float*)d_in[10];
    const float* bt   = (const float*)d_in[11];
    const float* Wmm  = (const float*)d_in[12];
    const float* bmm  = (const float*)d_in[13];
    const float* Wli  = (const float*)d_in[14];
    const float* bli  = (const float*)d_in[15];
    const float* Wih  = (const float*)d_in[16];
    const float* Whh  = (const float*)d_in[17];
    const float* bih  = (const float*)d_in[18];
    const float* bhh  = (const float*)d_in[19];
    const float* Wsm  = (const float*)d_in[20];
    const float* Wst  = (const float*)d_in[22];
    const float* Wo   = (const float*)d_in[24];
    const float* bo   = (const float*)d_in[25];
    float* out = (float*)d_out;

    float *tmpM, *tmpT, *xproj, *meanfeat, *bsum, *attw, *ctxT, *ctxpart, *ctxproj;
    __nv_bfloat16 *hA, *hB, *amot_bf, *atem_bf, *Wm_bf, *Wt_bf, *Wmm_bf, *Wih_bf, *Wo_bf;
    __nv_bfloat16 *mminp_bf, *xin_bf, *act_bf;
    cudaGetSymbolAddress((void**)&tmpM, g_tmpM);
    cudaGetSymbolAddress((void**)&tmpT, g_tmpT);
    cudaGetSymbolAddress((void**)&xproj, g_xproj);
    cudaGetSymbolAddress((void**)&meanfeat, g_meanfeat);
    cudaGetSymbolAddress((void**)&bsum, g_bsum);
    cudaGetSymbolAddress((void**)&hA, g_hbA);
    cudaGetSymbolAddress((void**)&hB, g_hbB);
    cudaGetSymbolAddress((void**)&attw, g_attw);
    cudaGetSymbolAddress((void**)&ctxT, g_ctxT);
    cudaGetSymbolAddress((void**)&ctxpart, g_ctxpart);
    cudaGetSymbolAddress((void**)&ctxproj, g_ctxproj);
    cudaGetSymbolAddress((void**)&amot_bf, g_amot_bf);
    cudaGetSymbolAddress((void**)&atem_bf, g_atem_bf);
    cudaGetSymbolAddress((void**)&Wm_bf, g_Wm_bf);
    cudaGetSymbolAddress((void**)&Wt_bf, g_Wt_bf);
    cudaGetSymbolAddress((void**)&Wmm_bf, g_Wmm_bf);
    cudaGetSymbolAddress((void**)&Wih_bf, g_Wih_bf);
    cudaGetSymbolAddress((void**)&Wo_bf, g_Wo_bf);
    cudaGetSymbolAddress((void**)&mminp_bf, g_mminp_bf);
    cudaGetSymbolAddress((void**)&xin_bf, g_xin_bf);
    cudaGetSymbolAddress((void**)&act_bf, g_act_bf);

    cudaFuncSetAttribute(lstm_persistent, cudaFuncAttributeMaxDynamicSharedMemorySize, LSTM_SMEMB);

    static cudaStream_t s2 = nullptr;
    static cudaEvent_t evF = nullptr, evJ = nullptr;
    if (!s2) {
        cudaStreamCreateWithFlags(&s2, cudaStreamNonBlocking);
        cudaEventCreateWithFlags(&evF, cudaEventDisableTiming);
        cudaEventCreateWithFlags(&evJ, cudaEventDisableTiming);
    }

    // ---- fork: attention path on s2 (depends only on inputs) ----
    cudaEventRecord(evF, 0);
    cudaStreamWaitEvent(s2, evF, 0);
    f2b_wo_kernel<<<(V_ * 128 + 255) / 256, 256, 0, s2>>>(Wo, Wo_bf);
    attn_scores<<<dim3(16, 2), 256, 0, s2>>>(tfeat, mfeat, Wst + 512, Wsm + 512, tlens, mlens, attw);
    attn_ctx<<<dim3(16, 8, 2), 128, 0, s2>>>(tfeat, mfeat, attw, ctxT);
    ctxproj_part<<<dim3(625, 4), 64, 0, s2>>>(ctxT, Wo, ctxpart);
    ctxproj_reduce<<<(16 * V_ + 255) / 256, 256, 0, s2>>>(ctxpart, bo, ctxproj);
    cudaEventRecord(evJ, s2);

    // ---- main path ----
    f2b_all_kernel<<<(F2B_N5 + 255) / 256, 256>>>(
        att_motion, amot_bf, att_tempo, atem_bf, Wm, Wm_bf,
        Wt, Wt_bf, Wmm, Wmm_bf, Wih, Wih_bf);

    bsum_kernel<<<8, 256>>>(bih, bhh, bsum);
    avgpool_kernel<<<128, 224>>>(att_tempo, att_motion, meanfeat);
    gemm_naive<<<(128 * 512 + 255) / 256, 256>>>(meanfeat, Wli, bli, xin_bf + 1280 * 512, 128, 512, 204);

    // both modality GEMMs in one launch (grid.z selects problem)
    gemm_mma<64><<<dim3(16, 10, 2), 256>>>(amot_bf, 1024, Wm_bf, 1024, bm, nullptr, 1, 0,
                                           tmpM, nullptr, 1024, 1024,
                                           atem_bf, Wt_bf, bt, tmpT);
    selfgate_kernel<<<dim3(1280, 2), 256>>>(tmpT, tmpM, mminp_bf);
    copy_emb<<<640, 256>>>(embeddings, mminp_bf);

    gemm_mma<64><<<dim3(8, 10), 256>>>(mminp_bf, 2560, Wmm_bf, 2560, bmm, nullptr, 1, 0,
                                       nullptr, xin_bf, 512, 2560);
    gemm_mma<64><<<dim3(32, 11), 256>>>(xin_bf, 512, Wih_bf, 512, bsum, nullptr, 1, 0,
                                        xproj, nullptr, 2048, 512);

    cudaMemsetAsync(hA, 0, B_ * H_ * sizeof(__nv_bfloat16));
    lstm_persistent<<<NBLK_LSTM, 256, LSTM_SMEMB>>>(xproj, Whh, act_bf, hA, hB);

    // ---- join, then final projection + log_softmax ----
    cudaStreamWaitEvent(0, evJ, 0);
    gemm_mma<80><<<dim3(125, 10), 256>>>(act_bf, 512, Wo_bf, 512, nullptr, ctxproj, 80, V_,
                                         out, nullptr, 10000, 512);
    logsoftmax_kernel<<<1280, 256, V_ * sizeof(float)>>>(out);
}